// round 2
// baseline (speedup 1.0000x reference)
#include <cuda_runtime.h>
#include <math.h>

#define D 4096
#define BB 512          // batch
#define N3 (3*D)

// ---------------- device scratch (no allocations allowed) ----------------
__device__ float g_h[BB*D];
__device__ float g_nt[(size_t)BB*N3];
__device__ float g_ma[BB*D];        // mod_alpha
__device__ float g_as[BB*D];        // softmax(prev_act)
__device__ float g_ars[BB*D];       // softmax(prev_rec_act)
__device__ float g_gsum[D];
__device__ float g_sdec[D];
__device__ float g_rmW[D], g_rsW[D], g_rmR[D], g_rsR[D];
__device__ float g_Wn[(size_t)D*D];
__device__ float g_Wrn[(size_t)D*D];
__device__ float g_rec[BB*D];
__device__ float g_recin[BB*D];
__device__ float g_act[BB*D];

// ---------------- block reduce ----------------
__device__ __forceinline__ float blk_reduce(float v, bool do_max) {
    __shared__ float sh[32];
    int lane = threadIdx.x & 31, w = threadIdx.x >> 5;
#pragma unroll
    for (int o = 16; o; o >>= 1) {
        float t = __shfl_xor_sync(0xffffffffu, v, o);
        v = do_max ? fmaxf(v, t) : v + t;
    }
    if (lane == 0) sh[w] = v;
    __syncthreads();
    int nw = (blockDim.x + 31) >> 5;
    if (w == 0) {
        v = (lane < nw) ? sh[lane] : (do_max ? -INFINITY : 0.f);
#pragma unroll
        for (int o = 16; o; o >>= 1) {
            float t = __shfl_xor_sync(0xffffffffu, v, o);
            v = do_max ? fmaxf(v, t) : v + t;
        }
        if (lane == 0) sh[0] = v;
    }
    __syncthreads();
    float r = sh[0];
    __syncthreads();   // allow sh reuse by next call
    return r;
}

// ---------------- row softmax (one block per row) ----------------
__global__ void row_softmax_kernel(const float* __restrict__ src, float* __restrict__ dst) {
    int row = blockIdx.x;
    const float* x = src + (size_t)row * D;
    float m = -INFINITY;
    for (int i = threadIdx.x; i < D; i += blockDim.x) m = fmaxf(m, x[i]);
    m = blk_reduce(m, true);
    float s = 0.f;
    for (int i = threadIdx.x; i < D; i += blockDim.x) s += expf(x[i] - m);
    s = blk_reduce(s, false);
    float inv = 1.f / s;
    for (int i = threadIdx.x; i < D; i += blockDim.x)
        dst[(size_t)row * D + i] = expf(x[i] - m) * inv;
}

// ---------------- per-row max & exp-sum for W softmax ----------------
__global__ void row_stats_kernel(const float* __restrict__ Wsrc,
                                 float* __restrict__ rmax, float* __restrict__ rsum) {
    int row = blockIdx.x;
    const float* x = Wsrc + (size_t)row * D;
    float m = -INFINITY;
    for (int i = threadIdx.x; i < D; i += blockDim.x) m = fmaxf(m, x[i]);
    m = blk_reduce(m, true);
    float s = 0.f;
    for (int i = threadIdx.x; i < D; i += blockDim.x) s += expf(x[i] - m);
    s = blk_reduce(s, false);
    if (threadIdx.x == 0) { rmax[row] = m; rsum[row] = s; }
}

// ---------------- layernorm (one block per row) ----------------
__global__ void layernorm_kernel(const float* __restrict__ src,
                                 const float* __restrict__ g, const float* __restrict__ b,
                                 float* __restrict__ dst) {
    int row = blockIdx.x;
    const float* x = src + (size_t)row * D;
    float s = 0.f, s2 = 0.f;
    for (int i = threadIdx.x; i < D; i += blockDim.x) { float v = x[i]; s += v; s2 += v * v; }
    s = blk_reduce(s, false);
    s2 = blk_reduce(s2, false);
    float mean = s * (1.f / D);
    float var = s2 * (1.f / D) - mean * mean;
    float rstd = rsqrtf(var + 1e-5f);
    for (int i = threadIdx.x; i < D; i += blockDim.x)
        dst[(size_t)row * D + i] = (x[i] - mean) * rstd * g[i] + b[i];
}

// ---------------- neuromodulators ----------------
__global__ void zero_kernel(float* p, int n) {
    int i = blockIdx.x * blockDim.x + threadIdx.x;
    if (i < n) p[i] = 0.f;
}

__device__ __forceinline__ float sigm(float x) { return 1.f / (1.f + expf(-x)); }

// grid (D/256, 8): each block covers 256 columns x 64 batch rows
__global__ void neuromod_partial(const float* __restrict__ nt,
                                 const float* __restrict__ dopamine,
                                 const float* __restrict__ serotonin,
                                 const float* __restrict__ gaba,
                                 const float* __restrict__ alpha,
                                 float* __restrict__ mod_alpha,
                                 float* __restrict__ gsum) {
    int j = blockIdx.x * blockDim.x + threadIdx.x;
    int b0 = blockIdx.y * (BB / 8);
    float a = alpha[j];
    float gs = 0.f;
    for (int b = b0; b < b0 + BB / 8; b++) {
        const float* p = nt + (size_t)b * N3 + 3 * j;
        float pd = p[0], ps = p[1], pg = p[2];
        float inv = 1.f / fmaxf(ps, 1e-6f);
        size_t bi = (size_t)b * D + j;
        float dop = tanhf(dopamine[bi] + pd * inv);
        float ser = sigm(serotonin[bi] + ps);
        float gab = sigm(gaba[bi] + pg * inv);
        gs += gab;
        mod_alpha[bi] = a * dop * ser;
    }
    atomicAdd(&gsum[j], gs);
}

__global__ void sdecay_kernel(const float* __restrict__ gsum,
                              const float* __restrict__ decay,
                              float* __restrict__ sdec) {
    int j = blockIdx.x * blockDim.x + threadIdx.x;
    sdec[j] = decay[j] * sigm(gsum[j] * (1.f / BB));
}

// ---------------- generic tiled SGEMM ----------------
// LAYOUT: 0 = NT (A[M,K], B[N,K]), 1 = NN (A[M,K], B[K,N]), 2 = TN (A[K,M], B[K,N])
// EPI:    0 = store, 1 = +bias relu, 2 = +bias, 3 = +addmat relu, 4 = Hebbian W update
template<int BM, int BN, int BK, int TM, int TN, int LAYOUT, int EPI>
__global__ void __launch_bounds__(256)
gemm_kernel(const float* __restrict__ A, const float* __restrict__ B,
            float* __restrict__ C, int M, int N, int K,
            const float* __restrict__ bias, const float* __restrict__ addmat,
            const float* __restrict__ Wold, const float* __restrict__ rmax,
            const float* __restrict__ rsum, const float* __restrict__ sdecay) {
    constexpr int THREADS = (BM / TM) * (BN / TN);
    constexpr int TX = BN / TN;
    __shared__ __align__(16) float As[BK][BM + 4];
    __shared__ __align__(16) float Bs[BK][BN + 4];
    const int tid = threadIdx.x;
    const int tx = tid % TX;
    const int ty = tid / TX;
    const int m0 = blockIdx.y * BM;
    const int n0 = blockIdx.x * BN;

    float acc[TM][TN];
#pragma unroll
    for (int i = 0; i < TM; i++)
#pragma unroll
        for (int j = 0; j < TN; j++) acc[i][j] = 0.f;

    for (int k0 = 0; k0 < K; k0 += BK) {
        if (LAYOUT == 2) {              // A in [K,M]
#pragma unroll
            for (int i = 0; i < (BM * BK) / THREADS; i++) {
                int e = tid + i * THREADS;
                int k = e / BM, m = e % BM;
                As[k][m] = A[(size_t)(k0 + k) * M + (m0 + m)];
            }
        } else {                        // A in [M,K]
#pragma unroll
            for (int i = 0; i < (BM * BK) / THREADS; i++) {
                int e = tid + i * THREADS;
                int m = e / BK, k = e % BK;
                As[k][m] = A[(size_t)(m0 + m) * K + (k0 + k)];
            }
        }
        if (LAYOUT == 0) {              // B in [N,K]
#pragma unroll
            for (int i = 0; i < (BN * BK) / THREADS; i++) {
                int e = tid + i * THREADS;
                int n = e / BK, k = e % BK;
                Bs[k][n] = B[(size_t)(n0 + n) * K + (k0 + k)];
            }
        } else {                        // B in [K,N]
#pragma unroll
            for (int i = 0; i < (BN * BK) / THREADS; i++) {
                int e = tid + i * THREADS;
                int k = e / BN, n = e % BN;
                Bs[k][n] = B[(size_t)(k0 + k) * N + (n0 + n)];
            }
        }
        __syncthreads();
#pragma unroll
        for (int kk = 0; kk < BK; kk++) {
            float a[TM], b[TN];
#pragma unroll
            for (int i = 0; i < TM; i += 4) {
                float4 t = *reinterpret_cast<const float4*>(&As[kk][ty * TM + i]);
                a[i] = t.x; a[i + 1] = t.y; a[i + 2] = t.z; a[i + 3] = t.w;
            }
#pragma unroll
            for (int j = 0; j < TN; j += 4) {
                float4 t = *reinterpret_cast<const float4*>(&Bs[kk][tx * TN + j]);
                b[j] = t.x; b[j + 1] = t.y; b[j + 2] = t.z; b[j + 3] = t.w;
            }
#pragma unroll
            for (int i = 0; i < TM; i++)
#pragma unroll
                for (int j = 0; j < TN; j++) acc[i][j] = fmaf(a[i], b[j], acc[i][j]);
        }
        __syncthreads();
    }

#pragma unroll
    for (int i = 0; i < TM; i++) {
        int m = m0 + ty * TM + i;
        float sd = 0.f, rm = 0.f, rs = 1.f;
        if (EPI == 4) { sd = sdecay[m]; rm = rmax[m]; rs = rsum[m]; }
#pragma unroll
        for (int j = 0; j < TN; j++) {
            int n = n0 + tx * TN + j;
            size_t idx = (size_t)m * N + n;
            float v = acc[i][j];
            if (EPI == 1)      { v += bias[n]; v = fmaxf(v, 0.f); }
            else if (EPI == 2) { v += bias[n]; }
            else if (EPI == 3) { v += addmat[idx]; v = fmaxf(v, 0.f); }
            else if (EPI == 4) {
                float w = Wold[idx];
                float p = expf(w - rm) / rs;                 // row softmax of W
                v = w + p * (v * (1.0f / BB)) - sd * w;      // W + wu - sd*W
            }
            C[idx] = v;
        }
    }
}

// ---------------- host launch ----------------
template<typename T>
static float* sym_addr(T& sym) { void* p = nullptr; cudaGetSymbolAddress(&p, sym); return (float*)p; }

extern "C" void kernel_launch(void* const* d_in, const int* in_sizes, int n_in,
                              void* d_out, int out_size) {
    const float* x        = (const float*)d_in[0];
    const float* prev_act = (const float*)d_in[1];
    const float* prev_rec = (const float*)d_in[2];
    const float* dopamine = (const float*)d_in[3];
    const float* serotonin= (const float*)d_in[4];
    const float* gaba     = (const float*)d_in[5];
    const float* W        = (const float*)d_in[6];
    const float* Wr       = (const float*)d_in[7];
    const float* alpha    = (const float*)d_in[8];
    const float* decay    = (const float*)d_in[9];
    const float* gact     = (const float*)d_in[10];
    const float* bact     = (const float*)d_in[11];
    const float* grec     = (const float*)d_in[12];
    const float* brec     = (const float*)d_in[13];
    const float* p1w      = (const float*)d_in[14];
    const float* p1b      = (const float*)d_in[15];
    const float* p2w      = (const float*)d_in[16];
    const float* p2b      = (const float*)d_in[17];
    float* out = (float*)d_out;

    float *h    = sym_addr(g_h),    *nt   = sym_addr(g_nt),   *ma   = sym_addr(g_ma);
    float *as_  = sym_addr(g_as),   *ars  = sym_addr(g_ars);
    float *gsum = sym_addr(g_gsum), *sdec = sym_addr(g_sdec);
    float *rmW  = sym_addr(g_rmW),  *rsW  = sym_addr(g_rsW);
    float *rmR  = sym_addr(g_rmR),  *rsR  = sym_addr(g_rsR);
    float *Wn   = sym_addr(g_Wn),   *Wrn  = sym_addr(g_Wrn);
    float *rec  = sym_addr(g_rec),  *recin= sym_addr(g_recin), *act = sym_addr(g_act);

    // softmaxes + W row stats (independent)
    row_softmax_kernel<<<BB, 256>>>(prev_act, as_);
    row_softmax_kernel<<<BB, 256>>>(prev_rec, ars);
    row_stats_kernel<<<D, 256>>>(W, rmW, rsW);
    row_stats_kernel<<<D, 256>>>(Wr, rmR, rsR);

    // h = relu(prev_act @ p1_w^T + p1_b)
    gemm_kernel<64,128,16,4,8,0,1><<<dim3(D/128, BB/64), 256>>>(
        prev_act, p1w, h, BB, D, D, p1b, nullptr, nullptr, nullptr, nullptr, nullptr);
    // nt = h @ p2_w^T + p2_b
    gemm_kernel<64,128,16,4,8,0,2><<<dim3(N3/128, BB/64), 256>>>(
        h, p2w, nt, BB, N3, D, p2b, nullptr, nullptr, nullptr, nullptr, nullptr);

    // neuromodulators -> mod_alpha, scaled_decay
    zero_kernel<<<D/256, 256>>>(gsum, D);
    neuromod_partial<<<dim3(D/256, 8), 256>>>(nt, dopamine, serotonin, gaba, alpha, ma, gsum);
    sdecay_kernel<<<D/256, 256>>>(gsum, decay, sdec);

    // W_new / Wr_new : corr GEMM (TN, K=512) fused with Hebbian update epilogue
    gemm_kernel<128,128,16,8,8,2,4><<<dim3(D/128, D/128), 256>>>(
        as_, ma, Wn, D, D, BB, nullptr, nullptr, W, rmW, rsW, sdec);
    gemm_kernel<128,128,16,8,8,2,4><<<dim3(D/128, D/128), 256>>>(
        ars, ma, Wrn, D, D, BB, nullptr, nullptr, Wr, rmR, rsR, sdec);

    // rec = prev_act @ Wr_new ; rec_in = LN(rec)
    gemm_kernel<64,128,16,4,8,1,0><<<dim3(D/128, BB/64), 256>>>(
        prev_act, Wrn, rec, BB, D, D, nullptr, nullptr, nullptr, nullptr, nullptr, nullptr);
    layernorm_kernel<<<BB, 256>>>(rec, grec, brec, recin);

    // act = relu(x @ W_new + rec_in) ; out = LN(act)
    gemm_kernel<64,128,16,4,8,1,3><<<dim3(D/128, BB/64), 256>>>(
        x, Wn, act, BB, D, D, nullptr, recin, nullptr, nullptr, nullptr, nullptr);
    layernorm_kernel<<<BB, 256>>>(act, gact, bact, out);
}

// round 4
// speedup vs baseline: 7.9936x; 7.9936x over previous
#include <cuda_runtime.h>
#include <cuda_bf16.h>
#include <math.h>
#include <stdint.h>

#define D 4096
#define BB 512
#define N3 (3*D)
#define SMEM_BYTES (2*65536 + 1024)
#define IDESC_BF16 ((1u<<4)|(1u<<7)|(1u<<10)|(16u<<17)|(8u<<24))

// tcgen05 only exists on arch-specific targets (sm_103a etc.)
#if defined(__CUDA_ARCH_FEAT_SM103_ALL) || defined(__CUDA_ARCH_FEAT_SM100_ALL) || \
    defined(__CUDA_ARCH_FEAT_SM101_ALL) || \
    (defined(__CUDA_ARCH_SPECIFIC__) && (__CUDA_ARCH_SPECIFIC__ >= 1000)) || \
    (defined(__CUDA_ARCH_FAMILY_SPECIFIC__) && (__CUDA_ARCH_FAMILY_SPECIFIC__ >= 1000))
#define TC_OK 1
#else
#define TC_OK 0
#endif

// ---------------- device scratch ----------------
__device__ __nv_bfloat16 g_pa_h[BB*D],  g_pa_l[BB*D];
__device__ __nv_bfloat16 g_x_h[BB*D],   g_x_l[BB*D];
__device__ __nv_bfloat16 g_h_h[BB*D],   g_h_l[BB*D];
__device__ __nv_bfloat16 g_p1_h[(size_t)D*D],  g_p1_l[(size_t)D*D];
__device__ __nv_bfloat16 g_p2_h[(size_t)N3*D], g_p2_l[(size_t)N3*D];
__device__ __nv_bfloat16 g_asT_h[(size_t)D*BB],  g_asT_l[(size_t)D*BB];
__device__ __nv_bfloat16 g_arsT_h[(size_t)D*BB], g_arsT_l[(size_t)D*BB];
__device__ __nv_bfloat16 g_maT_h[(size_t)D*BB],  g_maT_l[(size_t)D*BB];
__device__ __nv_bfloat16 g_WnT_h[(size_t)D*D],  g_WnT_l[(size_t)D*D];
__device__ __nv_bfloat16 g_WrT_h[(size_t)D*D],  g_WrT_l[(size_t)D*D];
__device__ float g_nt[(size_t)BB*N3];
__device__ float g_rec[BB*D], g_recin[BB*D], g_act[BB*D];
__device__ float g_gsum[D], g_sdec[D], g_rmW[D], g_rsW[D], g_rmR[D], g_rsR[D];

// ---------------- helpers ----------------
__device__ __forceinline__ uint32_t s2u(const void* p) {
    uint32_t a;
    asm("{ .reg .u64 t; cvta.to.shared.u64 t, %1; cvt.u32.u64 %0, t; }" : "=r"(a) : "l"(p));
    return a;
}
__device__ __forceinline__ uint32_t sw128(uint32_t o) { return o ^ ((o >> 3) & 0x70); }
__device__ __forceinline__ void split2(float v, __nv_bfloat16& h, __nv_bfloat16& l) {
    h = __float2bfloat16(v);
    l = __float2bfloat16(v - __bfloat162float(h));
}
__device__ __forceinline__ float sigm(float x) { return 1.f / (1.f + expf(-x)); }

#if TC_OK
__device__ __forceinline__ void cp16(uint32_t d, const void* g) {
    asm volatile("cp.async.cg.shared.global [%0], [%1], 16;" :: "r"(d), "l"(g));
}
__device__ __forceinline__ uint64_t sdesc(uint32_t a) {
    return 0x4000404000010000ull | ((uint64_t)(a >> 4) & 0x3FFFull);
}
__device__ __forceinline__ void mma_bf16(uint32_t d, uint64_t ad, uint64_t bd, uint32_t en) {
    asm volatile(
        "{\n\t.reg .pred p;\n\t"
        "setp.ne.u32 p, %5, 0;\n\t"
        "tcgen05.mma.cta_group::1.kind::f16 [%0], %1, %2, %3, {%4, %4, %4, %4}, p;\n\t}"
        :: "r"(d), "l"(ad), "l"(bd), "r"(IDESC_BF16), "r"(0u), "r"(en) : "memory");
}
__device__ __forceinline__ void mma_commit(uint32_t mb) {
    asm volatile("tcgen05.commit.cta_group::1.mbarrier::arrive::one.shared::cluster.b64 [%0];"
                 :: "r"(mb) : "memory");
}
__device__ __forceinline__ void mbar_init(uint32_t mb, uint32_t cnt) {
    asm volatile("mbarrier.init.shared.b64 [%0], %1;" :: "r"(mb), "r"(cnt) : "memory");
}
__device__ __forceinline__ void mbar_wait(uint32_t mb, uint32_t par) {
    asm volatile(
        "{\n\t.reg .pred P;\nW%=:\n\t"
        "mbarrier.try_wait.parity.shared.b64 P, [%0], %1;\n\t"
        "@!P bra W%=;\n\t}"
        :: "r"(mb), "r"(par) : "memory");
}
__device__ __forceinline__ void ldtm32(uint32_t* r, uint32_t a) {
    asm volatile(
        "tcgen05.ld.sync.aligned.32x32b.x32.b32 "
        "{%0,%1,%2,%3,%4,%5,%6,%7,%8,%9,%10,%11,%12,%13,%14,%15,"
        "%16,%17,%18,%19,%20,%21,%22,%23,%24,%25,%26,%27,%28,%29,%30,%31}, [%32];"
        : "=r"(r[0]),"=r"(r[1]),"=r"(r[2]),"=r"(r[3]),"=r"(r[4]),"=r"(r[5]),"=r"(r[6]),"=r"(r[7]),
          "=r"(r[8]),"=r"(r[9]),"=r"(r[10]),"=r"(r[11]),"=r"(r[12]),"=r"(r[13]),"=r"(r[14]),"=r"(r[15]),
          "=r"(r[16]),"=r"(r[17]),"=r"(r[18]),"=r"(r[19]),"=r"(r[20]),"=r"(r[21]),"=r"(r[22]),"=r"(r[23]),
          "=r"(r[24]),"=r"(r[25]),"=r"(r[26]),"=r"(r[27]),"=r"(r[28]),"=r"(r[29]),"=r"(r[30]),"=r"(r[31])
        : "r"(a));
}
#endif

// ---------------- GEMM: C[m,n] = sum_k A[m,k]*B[n,k] (bf16 hi/lo, 3 products) ----------------
// EPI: 0 fp32 store; 1 +bias relu -> bf16 split; 2 +bias fp32; 3 +addmat relu fp32;
//      4 Hebbian -> transposed bf16 split
template<int EPI>
__global__ void __launch_bounds__(256, 1)
mma_gemm(const __nv_bfloat16* __restrict__ Ah, const __nv_bfloat16* __restrict__ Al,
         const __nv_bfloat16* __restrict__ Bh, const __nv_bfloat16* __restrict__ Bl,
         int K, int ldC, float* __restrict__ C,
         const float* __restrict__ bias, const float* __restrict__ addmat,
         const float* __restrict__ Wold, const float* __restrict__ rmax,
         const float* __restrict__ rsum, const float* __restrict__ sdec,
         __nv_bfloat16* __restrict__ Oh, __nv_bfloat16* __restrict__ Ol) {
    extern __shared__ char dsm[];
    const int tid = threadIdx.x;
    const int m0 = blockIdx.y * 128, n0 = blockIdx.x * 128;

#if TC_OK
    __shared__ uint32_t s_tm;
    __shared__ __align__(8) uint64_t s_mb[2];
    const int wid = tid >> 5, lid = tid & 31;
    uint32_t tile0 = (s2u(dsm) + 1023u) & ~1023u;
    uint32_t mbA[2] = { s2u(&s_mb[0]), s2u(&s_mb[1]) };

    if (wid == 0) {
        asm volatile("tcgen05.alloc.cta_group::1.sync.aligned.shared::cta.b32 [%0], %1;"
                     :: "r"(s2u(&s_tm)), "r"(128u) : "memory");
        asm volatile("tcgen05.relinquish_alloc_permit.cta_group::1.sync.aligned;");
    }
    if (tid == 0) { mbar_init(mbA[0], 1); mbar_init(mbA[1], 1); }
    __syncthreads();
    const uint32_t tm = s_tm;

    const __nv_bfloat16* srcs[4] = {
        Ah + (size_t)m0 * K, Al + (size_t)m0 * K,
        Bh + (size_t)n0 * K, Bl + (size_t)n0 * K };

    const int NC = K >> 6;
    for (int i = 0; i < NC; i++) {
        const uint32_t mb = mbA[i & 1];
        if (i >= 2) mbar_wait(mb, ((i - 2) >> 1) & 1);
        uint32_t base = tile0 + (i & 1) * 65536;
#pragma unroll
        for (int p = 0; p < 4; p++) {
            const __nv_bfloat16* s = srcs[p] + i * 64;
            uint32_t pb = base + p * 16384;
#pragma unroll
            for (int t = 0; t < 4; t++) {
                int idx = tid + t * 256;
                int r = idx >> 3, c = idx & 7;
                cp16(pb + sw128(r * 128 + c * 16), s + (size_t)r * K + c * 8);
            }
        }
        asm volatile("cp.async.commit_group;" ::: "memory");
        asm volatile("cp.async.wait_group 0;" ::: "memory");
        __syncthreads();
        if (tid == 0) {
            asm volatile("fence.proxy.async.shared::cta;" ::: "memory");
            uint64_t ah = sdesc(base),          al = sdesc(base + 16384);
            uint64_t bh = sdesc(base + 32768),  bl = sdesc(base + 49152);
#pragma unroll
            for (int s4 = 0; s4 < 4; s4++) {
                mma_bf16(tm, ah + 2*s4, bh + 2*s4, (i > 0) | (s4 > 0));
                mma_bf16(tm, ah + 2*s4, bl + 2*s4, 1);
                mma_bf16(tm, al + 2*s4, bh + 2*s4, 1);
            }
            mma_commit(mb);
        }
    }
    mbar_wait(mbA[(NC-1) & 1], ((NC-1) >> 1) & 1);
    mbar_wait(mbA[(NC-2) & 1], ((NC-2) >> 1) & 1);
    asm volatile("tcgen05.fence::after_thread_sync;" ::: "memory");

    if (wid < 4) {
        const int m = m0 + wid * 32 + lid;
        float sd = 0.f, rm = 0.f, irs = 1.f;
        if (EPI == 4) { sd = sdec[m]; rm = rmax[m]; irs = 1.f / rsum[m]; }
#pragma unroll
        for (int cb = 0; cb < 4; cb++) {
            uint32_t rr[32];
            ldtm32(rr, tm + cb * 32);
            asm volatile("tcgen05.wait::ld.sync.aligned;" ::: "memory");
            const int nb = n0 + cb * 32;
            if (EPI == 0) {
                float4* c4 = (float4*)(C + (size_t)m * ldC + nb);
#pragma unroll
                for (int q = 0; q < 8; q++)
                    c4[q] = make_float4(__uint_as_float(rr[4*q]), __uint_as_float(rr[4*q+1]),
                                        __uint_as_float(rr[4*q+2]), __uint_as_float(rr[4*q+3]));
            } else if (EPI == 1) {
#pragma unroll
                for (int j = 0; j < 32; j += 2) {
                    float v0 = fmaxf(__uint_as_float(rr[j])   + bias[nb+j],   0.f);
                    float v1 = fmaxf(__uint_as_float(rr[j+1]) + bias[nb+j+1], 0.f);
                    __nv_bfloat162 th, tl;
                    split2(v0, th.x, tl.x); split2(v1, th.y, tl.y);
                    *(__nv_bfloat162*)(Oh + (size_t)m * ldC + nb + j) = th;
                    *(__nv_bfloat162*)(Ol + (size_t)m * ldC + nb + j) = tl;
                }
            } else if (EPI == 2) {
                float4* c4 = (float4*)(C + (size_t)m * ldC + nb);
#pragma unroll
                for (int q = 0; q < 8; q++)
                    c4[q] = make_float4(__uint_as_float(rr[4*q])   + bias[nb+4*q],
                                        __uint_as_float(rr[4*q+1]) + bias[nb+4*q+1],
                                        __uint_as_float(rr[4*q+2]) + bias[nb+4*q+2],
                                        __uint_as_float(rr[4*q+3]) + bias[nb+4*q+3]);
            } else if (EPI == 3) {
                const float4* a4 = (const float4*)(addmat + (size_t)m * ldC + nb);
                float4* c4 = (float4*)(C + (size_t)m * ldC + nb);
#pragma unroll
                for (int q = 0; q < 8; q++) {
                    float4 a = a4[q];
                    c4[q] = make_float4(fmaxf(__uint_as_float(rr[4*q])   + a.x, 0.f),
                                        fmaxf(__uint_as_float(rr[4*q+1]) + a.y, 0.f),
                                        fmaxf(__uint_as_float(rr[4*q+2]) + a.z, 0.f),
                                        fmaxf(__uint_as_float(rr[4*q+3]) + a.w, 0.f));
                }
            } else { // Hebbian: W_new = W + softmax(W)*corr/B - sd*W, stored transposed
                const float4* w4 = (const float4*)(Wold + (size_t)m * D + nb);
#pragma unroll
                for (int q = 0; q < 8; q++) {
                    float4 w = w4[q];
                    float wv[4] = { w.x, w.y, w.z, w.w };
#pragma unroll
                    for (int e = 0; e < 4; e++) {
                        int j = 4*q + e;
                        float p = expf(wv[e] - rm) * irs;
                        float o = wv[e] + p * (__uint_as_float(rr[j]) * (1.0f/BB)) - sd * wv[e];
                        __nv_bfloat16 hh, ll;
                        split2(o, hh, ll);
                        Oh[(size_t)(nb + j) * D + m] = hh;
                        Ol[(size_t)(nb + j) * D + m] = ll;
                    }
                }
            }
        }
    }
    __syncthreads();
    if (wid == 0)
        asm volatile("tcgen05.dealloc.cta_group::1.sync.aligned.b32 %0, %1;" :: "r"(tm), "r"(128u));

#else  // ---------- generic-target fallback: correct fp32 tiled GEMM ----------
    float* As = (float*)dsm;            // [16][132]
    float* Bs = As + 16 * 132;          // [16][132]
    const int tx = tid & 15, ty = tid >> 4;
    float acc[8][8];
#pragma unroll
    for (int i = 0; i < 8; i++)
#pragma unroll
        for (int j = 0; j < 8; j++) acc[i][j] = 0.f;

    for (int k0 = 0; k0 < K; k0 += 16) {
#pragma unroll
        for (int e = 0; e < 8; e++) {
            int idx = tid + e * 256;        // 2048 elements
            int r = idx >> 4, k = idx & 15;
            size_t ai = (size_t)(m0 + r) * K + k0 + k;
            size_t bi = (size_t)(n0 + r) * K + k0 + k;
            As[k * 132 + r] = __bfloat162float(Ah[ai]) + __bfloat162float(Al[ai]);
            Bs[k * 132 + r] = __bfloat162float(Bh[bi]) + __bfloat162float(Bl[bi]);
        }
        __syncthreads();
#pragma unroll
        for (int kk = 0; kk < 16; kk++) {
            float a[8], b[8];
#pragma unroll
            for (int i = 0; i < 8; i++) a[i] = As[kk * 132 + ty * 8 + i];
#pragma unroll
            for (int j = 0; j < 8; j++) b[j] = Bs[kk * 132 + tx * 8 + j];
#pragma unroll
            for (int i = 0; i < 8; i++)
#pragma unroll
                for (int j = 0; j < 8; j++) acc[i][j] = fmaf(a[i], b[j], acc[i][j]);
        }
        __syncthreads();
    }
#pragma unroll
    for (int i = 0; i < 8; i++) {
        int m = m0 + ty * 8 + i;
        float sd = 0.f, rm = 0.f, irs = 1.f;
        if (EPI == 4) { sd = sdec[m]; rm = rmax[m]; irs = 1.f / rsum[m]; }
#pragma unroll
        for (int j = 0; j < 8; j++) {
            int n = n0 + tx * 8 + j;
            float v = acc[i][j];
            if (EPI == 0) C[(size_t)m * ldC + n] = v;
            else if (EPI == 1) {
                v = fmaxf(v + bias[n], 0.f);
                __nv_bfloat16 hh, ll; split2(v, hh, ll);
                Oh[(size_t)m * ldC + n] = hh; Ol[(size_t)m * ldC + n] = ll;
            } else if (EPI == 2) C[(size_t)m * ldC + n] = v + bias[n];
            else if (EPI == 3) C[(size_t)m * ldC + n] = fmaxf(v + addmat[(size_t)m * ldC + n], 0.f);
            else {
                float w = Wold[(size_t)m * D + n];
                float p = expf(w - rm) * irs;
                float o = w + p * (v * (1.0f/BB)) - sd * w;
                __nv_bfloat16 hh, ll; split2(o, hh, ll);
                Oh[(size_t)n * D + m] = hh; Ol[(size_t)n * D + m] = ll;
            }
        }
    }
#endif
}

// ---------------- block reduce + elementwise ----------------
__device__ __forceinline__ float blk_reduce(float v, bool do_max) {
    __shared__ float sh[32];
    int lane = threadIdx.x & 31, w = threadIdx.x >> 5;
#pragma unroll
    for (int o = 16; o; o >>= 1) {
        float t = __shfl_xor_sync(0xffffffffu, v, o);
        v = do_max ? fmaxf(v, t) : v + t;
    }
    if (lane == 0) sh[w] = v;
    __syncthreads();
    if (w == 0) {
        v = (lane < (int)(blockDim.x >> 5)) ? sh[lane] : (do_max ? -INFINITY : 0.f);
#pragma unroll
        for (int o = 16; o; o >>= 1) {
            float t = __shfl_xor_sync(0xffffffffu, v, o);
            v = do_max ? fmaxf(v, t) : v + t;
        }
        if (lane == 0) sh[0] = v;
    }
    __syncthreads();
    float r = sh[0];
    __syncthreads();
    return r;
}

__global__ void row_softmax_t(const float* __restrict__ src,
                              __nv_bfloat16* __restrict__ dh, __nv_bfloat16* __restrict__ dl) {
    int row = blockIdx.x;
    const float* x = src + (size_t)row * D;
    float m = -INFINITY;
    for (int i = threadIdx.x; i < D; i += blockDim.x) m = fmaxf(m, x[i]);
    m = blk_reduce(m, true);
    float s = 0.f;
    for (int i = threadIdx.x; i < D; i += blockDim.x) s += expf(x[i] - m);
    s = blk_reduce(s, false);
    float inv = 1.f / s;
    for (int i = threadIdx.x; i < D; i += blockDim.x) {
        __nv_bfloat16 h, l;
        split2(expf(x[i] - m) * inv, h, l);
        dh[(size_t)i * BB + row] = h;
        dl[(size_t)i * BB + row] = l;
    }
}

__global__ void row_stats_kernel(const float* __restrict__ Wsrc,
                                 float* __restrict__ rmax, float* __restrict__ rsum) {
    int row = blockIdx.x;
    const float* x = Wsrc + (size_t)row * D;
    float m = -INFINITY;
    for (int i = threadIdx.x; i < D; i += blockDim.x) m = fmaxf(m, x[i]);
    m = blk_reduce(m, true);
    float s = 0.f;
    for (int i = threadIdx.x; i < D; i += blockDim.x) s += expf(x[i] - m);
    s = blk_reduce(s, false);
    if (threadIdx.x == 0) { rmax[row] = m; rsum[row] = s; }
}

__global__ void layernorm_kernel(const float* __restrict__ src,
                                 const float* __restrict__ g, const float* __restrict__ b,
                                 float* __restrict__ dst) {
    int row = blockIdx.x;
    const float* x = src + (size_t)row * D;
    float s = 0.f, s2 = 0.f;
    for (int i = threadIdx.x; i < D; i += blockDim.x) { float v = x[i]; s += v; s2 += v * v; }
    s = blk_reduce(s, false);
    s2 = blk_reduce(s2, false);
    float mean = s * (1.f / D);
    float rstd = rsqrtf(s2 * (1.f / D) - mean * mean + 1e-5f);
    for (int i = threadIdx.x; i < D; i += blockDim.x)
        dst[(size_t)row * D + i] = (x[i] - mean) * rstd * g[i] + b[i];
}

__global__ void zero_kernel(float* p, int n) {
    int i = blockIdx.x * blockDim.x + threadIdx.x;
    if (i < n) p[i] = 0.f;
}

__global__ void neuromod_partial(const float* __restrict__ nt,
                                 const float* __restrict__ dopamine,
                                 const float* __restrict__ serotonin,
                                 const float* __restrict__ gaba,
                                 const float* __restrict__ alpha,
                                 __nv_bfloat16* __restrict__ maTh,
                                 __nv_bfloat16* __restrict__ maTl,
                                 float* __restrict__ gsum) {
    int j = blockIdx.x * blockDim.x + threadIdx.x;
    int b0 = blockIdx.y * (BB / 8);
    float a = alpha[j];
    float gs = 0.f;
    for (int b = b0; b < b0 + BB / 8; b++) {
        const float* p = nt + (size_t)b * N3 + 3 * j;
        float pd = p[0], ps = p[1], pg = p[2];
        float inv = 1.f / fmaxf(ps, 1e-6f);
        size_t bi = (size_t)b * D + j;
        float dop = tanhf(dopamine[bi] + pd * inv);
        float ser = sigm(serotonin[bi] + ps);
        gs += sigm(gaba[bi] + pg * inv);
        __nv_bfloat16 h, l;
        split2(a * dop * ser, h, l);
        maTh[(size_t)j * BB + b] = h;
        maTl[(size_t)j * BB + b] = l;
    }
    atomicAdd(&gsum[j], gs);
}

__global__ void sdecay_kernel(const float* __restrict__ gsum,
                              const float* __restrict__ decay, float* __restrict__ sdec) {
    int j = blockIdx.x * blockDim.x + threadIdx.x;
    sdec[j] = decay[j] * sigm(gsum[j] * (1.f / BB));
}

__global__ void split_kernel(const float4* __restrict__ src,
                             __nv_bfloat16* __restrict__ dh, __nv_bfloat16* __restrict__ dl,
                             size_t n4) {
    size_t i = (size_t)blockIdx.x * blockDim.x + threadIdx.x;
    if (i >= n4) return;
    float4 v = src[i];
    __nv_bfloat162 h0, h1, l0, l1;
    split2(v.x, h0.x, l0.x); split2(v.y, h0.y, l0.y);
    split2(v.z, h1.x, l1.x); split2(v.w, h1.y, l1.y);
    ((__nv_bfloat162*)dh)[2*i]   = h0; ((__nv_bfloat162*)dh)[2*i+1] = h1;
    ((__nv_bfloat162*)dl)[2*i]   = l0; ((__nv_bfloat162*)dl)[2*i+1] = l1;
}

// ---------------- host ----------------
template<typename T>
static void* sym_addr(T& sym) { void* p = nullptr; cudaGetSymbolAddress(&p, sym); return p; }
#define BF(sym) ((__nv_bfloat16*)sym_addr(sym))
#define FP(sym) ((float*)sym_addr(sym))

extern "C" void kernel_launch(void* const* d_in, const int* in_sizes, int n_in,
                              void* d_out, int out_size) {
    const float* x        = (const float*)d_in[0];
    const float* prev_act = (const float*)d_in[1];
    const float* prev_rec = (const float*)d_in[2];
    const float* dopamine = (const float*)d_in[3];
    const float* serotonin= (const float*)d_in[4];
    const float* gaba     = (const float*)d_in[5];
    const float* W        = (const float*)d_in[6];
    const float* Wr       = (const float*)d_in[7];
    const float* alpha    = (const float*)d_in[8];
    const float* decay    = (const float*)d_in[9];
    const float* gact     = (const float*)d_in[10];
    const float* bact     = (const float*)d_in[11];
    const float* grec     = (const float*)d_in[12];
    const float* brec     = (const float*)d_in[13];
    const float* p1w      = (const float*)d_in[14];
    const float* p1b      = (const float*)d_in[15];
    const float* p2w      = (const float*)d_in[16];
    const float* p2b      = (const float*)d_in[17];
    float* out = (float*)d_out;

    static bool attr_done = false;
    if (!attr_done) {
        cudaFuncSetAttribute(mma_gemm<0>, cudaFuncAttributeMaxDynamicSharedMemorySize, SMEM_BYTES);
        cudaFuncSetAttribute(mma_gemm<1>, cudaFuncAttributeMaxDynamicSharedMemorySize, SMEM_BYTES);
        cudaFuncSetAttribute(mma_gemm<2>, cudaFuncAttributeMaxDynamicSharedMemorySize, SMEM_BYTES);
        cudaFuncSetAttribute(mma_gemm<3>, cudaFuncAttributeMaxDynamicSharedMemorySize, SMEM_BYTES);
        cudaFuncSetAttribute(mma_gemm<4>, cudaFuncAttributeMaxDynamicSharedMemorySize, SMEM_BYTES);
        attr_done = true;
    }

    // input splits
    split_kernel<<<(BB*D/4 + 255)/256, 256>>>((const float4*)prev_act, BF(g_pa_h), BF(g_pa_l), BB*D/4);
    split_kernel<<<(BB*D/4 + 255)/256, 256>>>((const float4*)x,        BF(g_x_h),  BF(g_x_l),  BB*D/4);
    split_kernel<<<((size_t)D*D/4 + 255)/256, 256>>>((const float4*)p1w, BF(g_p1_h), BF(g_p1_l), (size_t)D*D/4);
    split_kernel<<<((size_t)N3*D/4 + 255)/256, 256>>>((const float4*)p2w, BF(g_p2_h), BF(g_p2_l), (size_t)N3*D/4);

    // softmaxes (transposed splits) + W row stats
    row_softmax_t<<<BB, 256>>>(prev_act, BF(g_asT_h),  BF(g_asT_l));
    row_softmax_t<<<BB, 256>>>(prev_rec, BF(g_arsT_h), BF(g_arsT_l));
    row_stats_kernel<<<D, 256>>>(W,  FP(g_rmW), FP(g_rsW));
    row_stats_kernel<<<D, 256>>>(Wr, FP(g_rmR), FP(g_rsR));

    // h = relu(pa @ p1w^T + p1b)  -> bf16 split
    mma_gemm<1><<<dim3(D/128, BB/128), 256, SMEM_BYTES>>>(
        BF(g_pa_h), BF(g_pa_l), BF(g_p1_h), BF(g_p1_l), D, D,
        nullptr, p1b, nullptr, nullptr, nullptr, nullptr, nullptr, BF(g_h_h), BF(g_h_l));
    // nt = h @ p2w^T + p2b  (fp32)
    mma_gemm<2><<<dim3(N3/128, BB/128), 256, SMEM_BYTES>>>(
        BF(g_h_h), BF(g_h_l), BF(g_p2_h), BF(g_p2_l), D, N3,
        FP(g_nt), p2b, nullptr, nullptr, nullptr, nullptr, nullptr, nullptr, nullptr);

    // neuromodulators
    zero_kernel<<<D/256, 256>>>(FP(g_gsum), D);
    neuromod_partial<<<dim3(D/256, 8), 256>>>(FP(g_nt), dopamine, serotonin, gaba, alpha,
                                              BF(g_maT_h), BF(g_maT_l), FP(g_gsum));
    sdecay_kernel<<<D/256, 256>>>(FP(g_gsum), decay, FP(g_sdec));

    // Hebbian: W_new^T / Wr_new^T  (K = BB = 512)
    mma_gemm<4><<<dim3(D/128, D/128), 256, SMEM_BYTES>>>(
        BF(g_asT_h), BF(g_asT_l), BF(g_maT_h), BF(g_maT_l), BB, D,
        nullptr, nullptr, nullptr, W,  FP(g_rmW), FP(g_rsW), FP(g_sdec), BF(g_WnT_h), BF(g_WnT_l));
    mma_gemm<4><<<dim3(D/128, D/128), 256, SMEM_BYTES>>>(
        BF(g_arsT_h), BF(g_arsT_l), BF(g_maT_h), BF(g_maT_l), BB, D,
        nullptr, nullptr, nullptr, Wr, FP(g_rmR), FP(g_rsR), FP(g_sdec), BF(g_WrT_h), BF(g_WrT_l));

    // rec = pa @ Wr_new ; recin = LN(rec)
    mma_gemm<0><<<dim3(D/128, BB/128), 256, SMEM_BYTES>>>(
        BF(g_pa_h), BF(g_pa_l), BF(g_WrT_h), BF(g_WrT_l), D, D,
        FP(g_rec), nullptr, nullptr, nullptr, nullptr, nullptr, nullptr, nullptr, nullptr);
    layernorm_kernel<<<BB, 256>>>(FP(g_rec), grec, brec, FP(g_recin));

    // act = relu(x @ W_new + recin) ; out = LN(act)
    mma_gemm<3><<<dim3(D/128, BB/128), 256, SMEM_BYTES>>>(
        BF(g_x_h), BF(g_x_l), BF(g_WnT_h), BF(g_WnT_l), D, D,
        FP(g_act), nullptr, FP(g_recin), nullptr, nullptr, nullptr, nullptr, nullptr, nullptr);
    layernorm_kernel<<<BB, 256>>>(FP(g_act), gact, bact, out);
}

// round 5
// speedup vs baseline: 9.9361x; 1.2430x over previous
#include <cuda_runtime.h>
#include <cuda_bf16.h>
#include <math.h>
#include <stdint.h>

#define D 4096
#define BB 512
#define N3 (3*D)
#define STAGE_BYTES 65536
#define SMEM_BYTES (3*STAGE_BYTES + 1024)
#define IDESC_BF16 ((1u<<4)|(1u<<7)|(1u<<10)|(16u<<17)|(8u<<24))

// tcgen05 only exists on arch-specific targets (sm_103a etc.)
#if defined(__CUDA_ARCH_FEAT_SM103_ALL) || defined(__CUDA_ARCH_FEAT_SM100_ALL) || \
    defined(__CUDA_ARCH_FEAT_SM101_ALL) || \
    (defined(__CUDA_ARCH_SPECIFIC__) && (__CUDA_ARCH_SPECIFIC__ >= 1000)) || \
    (defined(__CUDA_ARCH_FAMILY_SPECIFIC__) && (__CUDA_ARCH_FAMILY_SPECIFIC__ >= 1000))
#define TC_OK 1
#else
#define TC_OK 0
#endif

// ---------------- device scratch ----------------
__device__ __nv_bfloat16 g_pa_h[BB*D],  g_pa_l[BB*D];
__device__ __nv_bfloat16 g_x_h[BB*D],   g_x_l[BB*D];
__device__ __nv_bfloat16 g_h_h[BB*D],   g_h_l[BB*D];
__device__ __nv_bfloat16 g_p1_h[(size_t)D*D],  g_p1_l[(size_t)D*D];
__device__ __nv_bfloat16 g_p2_h[(size_t)N3*D], g_p2_l[(size_t)N3*D];
__device__ __nv_bfloat16 g_asT_h[(size_t)D*BB],  g_asT_l[(size_t)D*BB];
__device__ __nv_bfloat16 g_arsT_h[(size_t)D*BB], g_arsT_l[(size_t)D*BB];
__device__ __nv_bfloat16 g_maT_h[(size_t)D*BB],  g_maT_l[(size_t)D*BB];
__device__ __nv_bfloat16 g_WnT_h[(size_t)D*D],  g_WnT_l[(size_t)D*D];
__device__ __nv_bfloat16 g_WrT_h[(size_t)D*D],  g_WrT_l[(size_t)D*D];
__device__ float g_nt[(size_t)BB*N3];
__device__ float g_rec[BB*D], g_recin[BB*D], g_act[BB*D];
__device__ float g_gsum[D], g_sdec[D], g_rmW[D], g_rsW[D], g_rmR[D], g_rsR[D];

// ---------------- helpers ----------------
__device__ __forceinline__ uint32_t s2u(const void* p) {
    uint32_t a;
    asm("{ .reg .u64 t; cvta.to.shared.u64 t, %1; cvt.u32.u64 %0, t; }" : "=r"(a) : "l"(p));
    return a;
}
__device__ __forceinline__ uint32_t sw128(uint32_t o) { return o ^ ((o >> 3) & 0x70); }
__device__ __forceinline__ void split2(float v, __nv_bfloat16& h, __nv_bfloat16& l) {
    h = __float2bfloat16(v);
    l = __float2bfloat16(v - __bfloat162float(h));
}
__device__ __forceinline__ float sigm(float x) { return 1.f / (1.f + expf(-x)); }

#if TC_OK
__device__ __forceinline__ void cp16(uint32_t d, const void* g) {
    asm volatile("cp.async.cg.shared.global [%0], [%1], 16;" :: "r"(d), "l"(g));
}
__device__ __forceinline__ uint64_t sdesc(uint32_t a) {
    return 0x4000404000010000ull | ((uint64_t)(a >> 4) & 0x3FFFull);
}
__device__ __forceinline__ void mma_bf16(uint32_t d, uint64_t ad, uint64_t bd, uint32_t en) {
    asm volatile(
        "{\n\t.reg .pred p;\n\t"
        "setp.ne.u32 p, %5, 0;\n\t"
        "tcgen05.mma.cta_group::1.kind::f16 [%0], %1, %2, %3, {%4, %4, %4, %4}, p;\n\t}"
        :: "r"(d), "l"(ad), "l"(bd), "r"(IDESC_BF16), "r"(0u), "r"(en) : "memory");
}
__device__ __forceinline__ void mma_commit(uint32_t mb) {
    asm volatile("tcgen05.commit.cta_group::1.mbarrier::arrive::one.shared::cluster.b64 [%0];"
                 :: "r"(mb) : "memory");
}
__device__ __forceinline__ void mbar_init(uint32_t mb, uint32_t cnt) {
    asm volatile("mbarrier.init.shared.b64 [%0], %1;" :: "r"(mb), "r"(cnt) : "memory");
}
__device__ __forceinline__ void mbar_wait(uint32_t mb, uint32_t par) {
    asm volatile(
        "{\n\t.reg .pred P;\nW%=:\n\t"
        "mbarrier.try_wait.parity.shared.b64 P, [%0], %1;\n\t"
        "@!P bra W%=;\n\t}"
        :: "r"(mb), "r"(par) : "memory");
}
__device__ __forceinline__ void ldtm32(uint32_t* r, uint32_t a) {
    asm volatile(
        "tcgen05.ld.sync.aligned.32x32b.x32.b32 "
        "{%0,%1,%2,%3,%4,%5,%6,%7,%8,%9,%10,%11,%12,%13,%14,%15,"
        "%16,%17,%18,%19,%20,%21,%22,%23,%24,%25,%26,%27,%28,%29,%30,%31}, [%32];"
        : "=r"(r[0]),"=r"(r[1]),"=r"(r[2]),"=r"(r[3]),"=r"(r[4]),"=r"(r[5]),"=r"(r[6]),"=r"(r[7]),
          "=r"(r[8]),"=r"(r[9]),"=r"(r[10]),"=r"(r[11]),"=r"(r[12]),"=r"(r[13]),"=r"(r[14]),"=r"(r[15]),
          "=r"(r[16]),"=r"(r[17]),"=r"(r[18]),"=r"(r[19]),"=r"(r[20]),"=r"(r[21]),"=r"(r[22]),"=r"(r[23]),
          "=r"(r[24]),"=r"(r[25]),"=r"(r[26]),"=r"(r[27]),"=r"(r[28]),"=r"(r[29]),"=r"(r[30]),"=r"(r[31])
        : "r"(a));
}
#endif

// ---------------- GEMM: C[m,n] = sum_k A[m,k]*B[n,k] (bf16 hi/lo, 3 products) ----------------
// grid: x = M/128 (fast-varying -> concurrent CTAs share B panel in L2), y = N/128
// EPI: 0 fp32 store; 1 +bias relu -> bf16 split; 2 +bias fp32; 3 +addmat relu fp32;
//      4 Hebbian -> transposed bf16 split
template<int EPI>
__global__ void __launch_bounds__(256, 1)
mma_gemm(const __nv_bfloat16* __restrict__ Ah, const __nv_bfloat16* __restrict__ Al,
         const __nv_bfloat16* __restrict__ Bh, const __nv_bfloat16* __restrict__ Bl,
         int K, int ldC, float* __restrict__ C,
         const float* __restrict__ bias, const float* __restrict__ addmat,
         const float* __restrict__ Wold, const float* __restrict__ rmax,
         const float* __restrict__ rsum, const float* __restrict__ sdec,
         __nv_bfloat16* __restrict__ Oh, __nv_bfloat16* __restrict__ Ol) {
    extern __shared__ char dsm[];
    const int tid = threadIdx.x;
    const int m0 = blockIdx.x * 128, n0 = blockIdx.y * 128;

#if TC_OK
    __shared__ uint32_t s_tm;
    __shared__ __align__(8) uint64_t s_mb[3];
    const int wid = tid >> 5, lid = tid & 31;
    uint32_t tile0 = (s2u(dsm) + 1023u) & ~1023u;
    uint32_t mbA[3] = { s2u(&s_mb[0]), s2u(&s_mb[1]), s2u(&s_mb[2]) };

    if (wid == 0) {
        asm volatile("tcgen05.alloc.cta_group::1.sync.aligned.shared::cta.b32 [%0], %1;"
                     :: "r"(s2u(&s_tm)), "r"(128u) : "memory");
        asm volatile("tcgen05.relinquish_alloc_permit.cta_group::1.sync.aligned;");
    }
    if (tid == 0) { mbar_init(mbA[0], 1); mbar_init(mbA[1], 1); mbar_init(mbA[2], 1); }
    __syncthreads();
    const uint32_t tm = s_tm;

    const __nv_bfloat16* srcs[4] = {
        Ah + (size_t)m0 * K, Al + (size_t)m0 * K,
        Bh + (size_t)n0 * K, Bl + (size_t)n0 * K };

    const int NC = K >> 6;

#define DO_COPY(i)                                                              \
    do {                                                                        \
        uint32_t base_ = tile0 + ((i) % 3) * STAGE_BYTES;                       \
        _Pragma("unroll")                                                       \
        for (int p = 0; p < 4; p++) {                                           \
            const __nv_bfloat16* s_ = srcs[p] + (i) * 64;                       \
            uint32_t pb_ = base_ + p * 16384;                                   \
            _Pragma("unroll")                                                   \
            for (int t = 0; t < 4; t++) {                                       \
                int idx_ = tid + t * 256;                                       \
                int r_ = idx_ >> 3, c_ = idx_ & 7;                              \
                cp16(pb_ + sw128(r_ * 128 + c_ * 16), s_ + (size_t)r_ * K + c_ * 8); \
            }                                                                   \
        }                                                                       \
        asm volatile("cp.async.commit_group;" ::: "memory");                    \
    } while (0)

    // prologue: stages 0 and 1 in flight
    DO_COPY(0);
    if (NC > 1) DO_COPY(1);

    for (int i = 0; i < NC; i++) {
        if (i + 2 < NC) {
            // buffer (i+2)%3 == (i-1)%3: wait for MMA chunk i-1 before overwriting
            if (i >= 1) mbar_wait(mbA[(i - 1) % 3], ((i - 1) / 3) & 1);
            DO_COPY(i + 2);
        }
        // ensure copy i complete (outstanding after this: the later stages only)
        if (i + 2 < NC)      asm volatile("cp.async.wait_group 2;" ::: "memory");
        else if (i + 1 < NC) asm volatile("cp.async.wait_group 1;" ::: "memory");
        else                 asm volatile("cp.async.wait_group 0;" ::: "memory");
        __syncthreads();
        if (tid == 0) {
            asm volatile("fence.proxy.async.shared::cta;" ::: "memory");
            uint32_t base = tile0 + (i % 3) * STAGE_BYTES;
            uint64_t ah = sdesc(base),          al = sdesc(base + 16384);
            uint64_t bh = sdesc(base + 32768),  bl = sdesc(base + 49152);
#pragma unroll
            for (int s4 = 0; s4 < 4; s4++) {
                mma_bf16(tm, ah + 2*s4, bh + 2*s4, (i > 0) | (s4 > 0));
                mma_bf16(tm, ah + 2*s4, bl + 2*s4, 1);
                mma_bf16(tm, al + 2*s4, bh + 2*s4, 1);
            }
            mma_commit(mbA[i % 3]);
        }
    }
#undef DO_COPY

    // drain: last three chunk commits (distinct mbars)
    for (int j = (NC >= 3 ? NC - 3 : 0); j < NC; j++)
        mbar_wait(mbA[j % 3], (j / 3) & 1);
    asm volatile("tcgen05.fence::after_thread_sync;" ::: "memory");

    if (wid < 4) {
        const int m = m0 + wid * 32 + lid;
        float sd = 0.f, rm = 0.f, irs = 1.f;
        if (EPI == 4) { sd = sdec[m]; rm = rmax[m]; irs = 1.f / rsum[m]; }
#pragma unroll
        for (int cb = 0; cb < 4; cb++) {
            uint32_t rr[32];
            ldtm32(rr, tm + cb * 32);
            asm volatile("tcgen05.wait::ld.sync.aligned;" ::: "memory");
            const int nb = n0 + cb * 32;
            if (EPI == 0) {
                float4* c4 = (float4*)(C + (size_t)m * ldC + nb);
#pragma unroll
                for (int q = 0; q < 8; q++)
                    c4[q] = make_float4(__uint_as_float(rr[4*q]), __uint_as_float(rr[4*q+1]),
                                        __uint_as_float(rr[4*q+2]), __uint_as_float(rr[4*q+3]));
            } else if (EPI == 1) {
#pragma unroll
                for (int j = 0; j < 32; j += 2) {
                    float v0 = fmaxf(__uint_as_float(rr[j])   + bias[nb+j],   0.f);
                    float v1 = fmaxf(__uint_as_float(rr[j+1]) + bias[nb+j+1], 0.f);
                    __nv_bfloat162 th, tl;
                    split2(v0, th.x, tl.x); split2(v1, th.y, tl.y);
                    *(__nv_bfloat162*)(Oh + (size_t)m * ldC + nb + j) = th;
                    *(__nv_bfloat162*)(Ol + (size_t)m * ldC + nb + j) = tl;
                }
            } else if (EPI == 2) {
                float4* c4 = (float4*)(C + (size_t)m * ldC + nb);
#pragma unroll
                for (int q = 0; q < 8; q++)
                    c4[q] = make_float4(__uint_as_float(rr[4*q])   + bias[nb+4*q],
                                        __uint_as_float(rr[4*q+1]) + bias[nb+4*q+1],
                                        __uint_as_float(rr[4*q+2]) + bias[nb+4*q+2],
                                        __uint_as_float(rr[4*q+3]) + bias[nb+4*q+3]);
            } else if (EPI == 3) {
                const float4* a4 = (const float4*)(addmat + (size_t)m * ldC + nb);
                float4* c4 = (float4*)(C + (size_t)m * ldC + nb);
#pragma unroll
                for (int q = 0; q < 8; q++) {
                    float4 a = a4[q];
                    c4[q] = make_float4(fmaxf(__uint_as_float(rr[4*q])   + a.x, 0.f),
                                        fmaxf(__uint_as_float(rr[4*q+1]) + a.y, 0.f),
                                        fmaxf(__uint_as_float(rr[4*q+2]) + a.z, 0.f),
                                        fmaxf(__uint_as_float(rr[4*q+3]) + a.w, 0.f));
                }
            } else { // Hebbian: W_new = W + softmax(W)*corr/B - sd*W, stored transposed
                const float4* w4 = (const float4*)(Wold + (size_t)m * D + nb);
#pragma unroll
                for (int q = 0; q < 8; q++) {
                    float4 w = w4[q];
                    float wv[4] = { w.x, w.y, w.z, w.w };
#pragma unroll
                    for (int e = 0; e < 4; e++) {
                        int j = 4*q + e;
                        float p = expf(wv[e] - rm) * irs;
                        float o = wv[e] + p * (__uint_as_float(rr[j]) * (1.0f/BB)) - sd * wv[e];
                        __nv_bfloat16 hh, ll;
                        split2(o, hh, ll);
                        Oh[(size_t)(nb + j) * D + m] = hh;
                        Ol[(size_t)(nb + j) * D + m] = ll;
                    }
                }
            }
        }
    }
    __syncthreads();
    if (wid == 0)
        asm volatile("tcgen05.dealloc.cta_group::1.sync.aligned.b32 %0, %1;" :: "r"(tm), "r"(128u));

#else  // ---------- generic-target fallback: correct fp32 tiled GEMM ----------
    float* As = (float*)dsm;
    float* Bs = As + 16 * 132;
    const int tx = tid & 15, ty = tid >> 4;
    float acc[8][8];
#pragma unroll
    for (int i = 0; i < 8; i++)
#pragma unroll
        for (int j = 0; j < 8; j++) acc[i][j] = 0.f;

    for (int k0 = 0; k0 < K; k0 += 16) {
#pragma unroll
        for (int e = 0; e < 8; e++) {
            int idx = tid + e * 256;
            int r = idx >> 4, k = idx & 15;
            size_t ai = (size_t)(m0 + r) * K + k0 + k;
            size_t bi = (size_t)(n0 + r) * K + k0 + k;
            As[k * 132 + r] = __bfloat162float(Ah[ai]) + __bfloat162float(Al[ai]);
            Bs[k * 132 + r] = __bfloat162float(Bh[bi]) + __bfloat162float(Bl[bi]);
        }
        __syncthreads();
#pragma unroll
        for (int kk = 0; kk < 16; kk++) {
            float a[8], b[8];
#pragma unroll
            for (int i = 0; i < 8; i++) a[i] = As[kk * 132 + ty * 8 + i];
#pragma unroll
            for (int j = 0; j < 8; j++) b[j] = Bs[kk * 132 + tx * 8 + j];
#pragma unroll
            for (int i = 0; i < 8; i++)
#pragma unroll
                for (int j = 0; j < 8; j++) acc[i][j] = fmaf(a[i], b[j], acc[i][j]);
        }
        __syncthreads();
    }
#pragma unroll
    for (int i = 0; i < 8; i++) {
        int m = m0 + ty * 8 + i;
        float sd = 0.f, rm = 0.f, irs = 1.f;
        if (EPI == 4) { sd = sdec[m]; rm = rmax[m]; irs = 1.f / rsum[m]; }
#pragma unroll
        for (int j = 0; j < 8; j++) {
            int n = n0 + tx * 8 + j;
            float v = acc[i][j];
            if (EPI == 0) C[(size_t)m * ldC + n] = v;
            else if (EPI == 1) {
                v = fmaxf(v + bias[n], 0.f);
                __nv_bfloat16 hh, ll; split2(v, hh, ll);
                Oh[(size_t)m * ldC + n] = hh; Ol[(size_t)m * ldC + n] = ll;
            } else if (EPI == 2) C[(size_t)m * ldC + n] = v + bias[n];
            else if (EPI == 3) C[(size_t)m * ldC + n] = fmaxf(v + addmat[(size_t)m * ldC + n], 0.f);
            else {
                float w = Wold[(size_t)m * D + n];
                float p = expf(w - rm) * irs;
                float o = w + p * (v * (1.0f/BB)) - sd * w;
                __nv_bfloat16 hh, ll; split2(o, hh, ll);
                Oh[(size_t)n * D + m] = hh; Ol[(size_t)n * D + m] = ll;
            }
        }
    }
#endif
}

// ---------------- block reduce + elementwise ----------------
__device__ __forceinline__ float blk_reduce(float v, bool do_max) {
    __shared__ float sh[32];
    int lane = threadIdx.x & 31, w = threadIdx.x >> 5;
#pragma unroll
    for (int o = 16; o; o >>= 1) {
        float t = __shfl_xor_sync(0xffffffffu, v, o);
        v = do_max ? fmaxf(v, t) : v + t;
    }
    if (lane == 0) sh[w] = v;
    __syncthreads();
    if (w == 0) {
        v = (lane < (int)(blockDim.x >> 5)) ? sh[lane] : (do_max ? -INFINITY : 0.f);
#pragma unroll
        for (int o = 16; o; o >>= 1) {
            float t = __shfl_xor_sync(0xffffffffu, v, o);
            v = do_max ? fmaxf(v, t) : v + t;
        }
        if (lane == 0) sh[0] = v;
    }
    __syncthreads();
    float r = sh[0];
    __syncthreads();
    return r;
}

__global__ void row_softmax_t(const float* __restrict__ src,
                              __nv_bfloat16* __restrict__ dh, __nv_bfloat16* __restrict__ dl) {
    int row = blockIdx.x;
    const float* x = src + (size_t)row * D;
    float m = -INFINITY;
    for (int i = threadIdx.x; i < D; i += blockDim.x) m = fmaxf(m, x[i]);
    m = blk_reduce(m, true);
    float s = 0.f;
    for (int i = threadIdx.x; i < D; i += blockDim.x) s += expf(x[i] - m);
    s = blk_reduce(s, false);
    float inv = 1.f / s;
    for (int i = threadIdx.x; i < D; i += blockDim.x) {
        __nv_bfloat16 h, l;
        split2(expf(x[i] - m) * inv, h, l);
        dh[(size_t)i * BB + row] = h;
        dl[(size_t)i * BB + row] = l;
    }
}

__global__ void row_stats_kernel(const float* __restrict__ Wsrc,
                                 float* __restrict__ rmax, float* __restrict__ rsum) {
    int row = blockIdx.x;
    const float* x = Wsrc + (size_t)row * D;
    float m = -INFINITY;
    for (int i = threadIdx.x; i < D; i += blockDim.x) m = fmaxf(m, x[i]);
    m = blk_reduce(m, true);
    float s = 0.f;
    for (int i = threadIdx.x; i < D; i += blockDim.x) s += expf(x[i] - m);
    s = blk_reduce(s, false);
    if (threadIdx.x == 0) { rmax[row] = m; rsum[row] = s; }
}

__global__ void layernorm_kernel(const float* __restrict__ src,
                                 const float* __restrict__ g, const float* __restrict__ b,
                                 float* __restrict__ dst) {
    int row = blockIdx.x;
    const float* x = src + (size_t)row * D;
    float s = 0.f, s2 = 0.f;
    for (int i = threadIdx.x; i < D; i += blockDim.x) { float v = x[i]; s += v; s2 += v * v; }
    s = blk_reduce(s, false);
    s2 = blk_reduce(s2, false);
    float mean = s * (1.f / D);
    float rstd = rsqrtf(s2 * (1.f / D) - mean * mean + 1e-5f);
    for (int i = threadIdx.x; i < D; i += blockDim.x)
        dst[(size_t)row * D + i] = (x[i] - mean) * rstd * g[i] + b[i];
}

__global__ void zero_kernel(float* p, int n) {
    int i = blockIdx.x * blockDim.x + threadIdx.x;
    if (i < n) p[i] = 0.f;
}

__global__ void neuromod_partial(const float* __restrict__ nt,
                                 const float* __restrict__ dopamine,
                                 const float* __restrict__ serotonin,
                                 const float* __restrict__ gaba,
                                 const float* __restrict__ alpha,
                                 __nv_bfloat16* __restrict__ maTh,
                                 __nv_bfloat16* __restrict__ maTl,
                                 float* __restrict__ gsum) {
    int j = blockIdx.x * blockDim.x + threadIdx.x;
    int b0 = blockIdx.y * (BB / 8);
    float a = alpha[j];
    float gs = 0.f;
    for (int b = b0; b < b0 + BB / 8; b++) {
        const float* p = nt + (size_t)b * N3 + 3 * j;
        float pd = p[0], ps = p[1], pg = p[2];
        float inv = 1.f / fmaxf(ps, 1e-6f);
        size_t bi = (size_t)b * D + j;
        float dop = tanhf(dopamine[bi] + pd * inv);
        float ser = sigm(serotonin[bi] + ps);
        gs += sigm(gaba[bi] + pg * inv);
        __nv_bfloat16 h, l;
        split2(a * dop * ser, h, l);
        maTh[(size_t)j * BB + b] = h;
        maTl[(size_t)j * BB + b] = l;
    }
    atomicAdd(&gsum[j], gs);
}

__global__ void sdecay_kernel(const float* __restrict__ gsum,
                              const float* __restrict__ decay, float* __restrict__ sdec) {
    int j = blockIdx.x * blockDim.x + threadIdx.x;
    sdec[j] = decay[j] * sigm(gsum[j] * (1.f / BB));
}

__global__ void split_kernel(const float4* __restrict__ src,
                             __nv_bfloat16* __restrict__ dh, __nv_bfloat16* __restrict__ dl,
                             size_t n4) {
    size_t i = (size_t)blockIdx.x * blockDim.x + threadIdx.x;
    if (i >= n4) return;
    float4 v = src[i];
    __nv_bfloat162 h0, h1, l0, l1;
    split2(v.x, h0.x, l0.x); split2(v.y, h0.y, l0.y);
    split2(v.z, h1.x, l1.x); split2(v.w, h1.y, l1.y);
    ((__nv_bfloat162*)dh)[2*i]   = h0; ((__nv_bfloat162*)dh)[2*i+1] = h1;
    ((__nv_bfloat162*)dl)[2*i]   = l0; ((__nv_bfloat162*)dl)[2*i+1] = l1;
}

// ---------------- host ----------------
template<typename T>
static void* sym_addr(T& sym) { void* p = nullptr; cudaGetSymbolAddress(&p, sym); return p; }
#define BF(sym) ((__nv_bfloat16*)sym_addr(sym))
#define FP(sym) ((float*)sym_addr(sym))

extern "C" void kernel_launch(void* const* d_in, const int* in_sizes, int n_in,
                              void* d_out, int out_size) {
    const float* x        = (const float*)d_in[0];
    const float* prev_act = (const float*)d_in[1];
    const float* prev_rec = (const float*)d_in[2];
    const float* dopamine = (const float*)d_in[3];
    const float* serotonin= (const float*)d_in[4];
    const float* gaba     = (const float*)d_in[5];
    const float* W        = (const float*)d_in[6];
    const float* Wr       = (const float*)d_in[7];
    const float* alpha    = (const float*)d_in[8];
    const float* decay    = (const float*)d_in[9];
    const float* gact     = (const float*)d_in[10];
    const float* bact     = (const float*)d_in[11];
    const float* grec     = (const float*)d_in[12];
    const float* brec     = (const float*)d_in[13];
    const float* p1w      = (const float*)d_in[14];
    const float* p1b      = (const float*)d_in[15];
    const float* p2w      = (const float*)d_in[16];
    const float* p2b      = (const float*)d_in[17];
    float* out = (float*)d_out;

    cudaFuncSetAttribute(mma_gemm<0>, cudaFuncAttributeMaxDynamicSharedMemorySize, SMEM_BYTES);
    cudaFuncSetAttribute(mma_gemm<1>, cudaFuncAttributeMaxDynamicSharedMemorySize, SMEM_BYTES);
    cudaFuncSetAttribute(mma_gemm<2>, cudaFuncAttributeMaxDynamicSharedMemorySize, SMEM_BYTES);
    cudaFuncSetAttribute(mma_gemm<3>, cudaFuncAttributeMaxDynamicSharedMemorySize, SMEM_BYTES);
    cudaFuncSetAttribute(mma_gemm<4>, cudaFuncAttributeMaxDynamicSharedMemorySize, SMEM_BYTES);

    // input splits
    split_kernel<<<(BB*D/4 + 255)/256, 256>>>((const float4*)prev_act, BF(g_pa_h), BF(g_pa_l), BB*D/4);
    split_kernel<<<(BB*D/4 + 255)/256, 256>>>((const float4*)x,        BF(g_x_h),  BF(g_x_l),  BB*D/4);
    split_kernel<<<((size_t)D*D/4 + 255)/256, 256>>>((const float4*)p1w, BF(g_p1_h), BF(g_p1_l), (size_t)D*D/4);
    split_kernel<<<((size_t)N3*D/4 + 255)/256, 256>>>((const float4*)p2w, BF(g_p2_h), BF(g_p2_l), (size_t)N3*D/4);

    // softmaxes (transposed splits) + W row stats
    row_softmax_t<<<BB, 256>>>(prev_act, BF(g_asT_h),  BF(g_asT_l));
    row_softmax_t<<<BB, 256>>>(prev_rec, BF(g_arsT_h), BF(g_arsT_l));
    row_stats_kernel<<<D, 256>>>(W,  FP(g_rmW), FP(g_rsW));
    row_stats_kernel<<<D, 256>>>(Wr, FP(g_rmR), FP(g_rsR));

    // h = relu(pa @ p1w^T + p1b)  -> bf16 split      (grid: x = M-blocks)
    mma_gemm<1><<<dim3(BB/128, D/128), 256, SMEM_BYTES>>>(
        BF(g_pa_h), BF(g_pa_l), BF(g_p1_h), BF(g_p1_l), D, D,
        nullptr, p1b, nullptr, nullptr, nullptr, nullptr, nullptr, BF(g_h_h), BF(g_h_l));
    // nt = h @ p2w^T + p2b  (fp32)
    mma_gemm<2><<<dim3(BB/128, N3/128), 256, SMEM_BYTES>>>(
        BF(g_h_h), BF(g_h_l), BF(g_p2_h), BF(g_p2_l), D, N3,
        FP(g_nt), p2b, nullptr, nullptr, nullptr, nullptr, nullptr, nullptr, nullptr);

    // neuromodulators
    zero_kernel<<<D/256, 256>>>(FP(g_gsum), D);
    neuromod_partial<<<dim3(D/256, 8), 256>>>(FP(g_nt), dopamine, serotonin, gaba, alpha,
                                              BF(g_maT_h), BF(g_maT_l), FP(g_gsum));
    sdecay_kernel<<<D/256, 256>>>(FP(g_gsum), decay, FP(g_sdec));

    // Hebbian: W_new^T / Wr_new^T  (K = BB = 512)
    mma_gemm<4><<<dim3(D/128, D/128), 256, SMEM_BYTES>>>(
        BF(g_asT_h), BF(g_asT_l), BF(g_maT_h), BF(g_maT_l), BB, D,
        nullptr, nullptr, nullptr, W,  FP(g_rmW), FP(g_rsW), FP(g_sdec), BF(g_WnT_h), BF(g_WnT_l));
    mma_gemm<4><<<dim3(D/128, D/128), 256, SMEM_BYTES>>>(
        BF(g_arsT_h), BF(g_arsT_l), BF(g_maT_h), BF(g_maT_l), BB, D,
        nullptr, nullptr, nullptr, Wr, FP(g_rmR), FP(g_rsR), FP(g_sdec), BF(g_WrT_h), BF(g_WrT_l));

    // rec = pa @ Wr_new ; recin = LN(rec)
    mma_gemm<0><<<dim3(BB/128, D/128), 256, SMEM_BYTES>>>(
        BF(g_pa_h), BF(g_pa_l), BF(g_WrT_h), BF(g_WrT_l), D, D,
        FP(g_rec), nullptr, nullptr, nullptr, nullptr, nullptr, nullptr, nullptr, nullptr);
    layernorm_kernel<<<BB, 256>>>(FP(g_rec), grec, brec, FP(g_recin));

    // act = relu(x @ W_new + recin) ; out = LN(act)
    mma_gemm<3><<<dim3(BB/128, D/128), 256, SMEM_BYTES>>>(
        BF(g_x_h), BF(g_x_l), BF(g_WnT_h), BF(g_WnT_l), D, D,
        FP(g_act), nullptr, FP(g_recin), nullptr, nullptr, nullptr, nullptr, nullptr, nullptr);
    layernorm_kernel<<<BB, 256>>>(FP(g_act), gact, bact, out);
}

// round 6
// speedup vs baseline: 11.7786x; 1.1854x over previous
#include <cuda_runtime.h>
#include <cuda_fp16.h>
#include <math.h>
#include <stdint.h>

#define D 4096
#define BB 512
#define N3 (3*D)
#define NSTAGE 4
#define STAGE_BYTES 49152
#define SMEM_BYTES (NSTAGE*STAGE_BYTES + 1024)
// kind::f16, f16 inputs (atype=btype=0), fp32 accum, M=128, N=128
#define IDESC_F16 ((1u<<4)|(16u<<17)|(8u<<24))

#if defined(__CUDA_ARCH_FEAT_SM103_ALL) || defined(__CUDA_ARCH_FEAT_SM100_ALL) || \
    defined(__CUDA_ARCH_FEAT_SM101_ALL) || \
    (defined(__CUDA_ARCH_SPECIFIC__) && (__CUDA_ARCH_SPECIFIC__ >= 1000)) || \
    (defined(__CUDA_ARCH_FAMILY_SPECIFIC__) && (__CUDA_ARCH_FAMILY_SPECIFIC__ >= 1000))
#define TC_OK 1
#else
#define TC_OK 0
#endif

// ---------------- device scratch ----------------
__device__ __half g_pa[BB*D], g_x[BB*D], g_h[BB*D];                 // A-side singles
__device__ __half g_p1_h[(size_t)D*D],  g_p1_l[(size_t)D*D];
__device__ __half g_p2_h[(size_t)N3*D], g_p2_l[(size_t)N3*D];
__device__ __half g_asT[(size_t)D*BB],  g_arsT[(size_t)D*BB];       // A-side singles
__device__ __half g_maT_h[(size_t)D*BB], g_maT_l[(size_t)D*BB];
__device__ __half g_WnT_h[(size_t)D*D], g_WnT_l[(size_t)D*D];
__device__ __half g_WrT_h[(size_t)D*D], g_WrT_l[(size_t)D*D];
__device__ float g_nt[(size_t)BB*N3];
__device__ float g_rec[BB*D], g_recin[BB*D], g_act[BB*D];
__device__ float g_gsum[D], g_sdec[D], g_rmW[D], g_rsW[D], g_rmR[D], g_rsR[D];

// ---------------- helpers ----------------
__device__ __forceinline__ uint32_t s2u(const void* p) {
    uint32_t a;
    asm("{ .reg .u64 t; cvta.to.shared.u64 t, %1; cvt.u32.u64 %0, t; }" : "=r"(a) : "l"(p));
    return a;
}
__device__ __forceinline__ uint32_t sw128(uint32_t o) { return o ^ ((o >> 3) & 0x70); }
__device__ __forceinline__ void split2h(float v, __half& h, __half& l) {
    h = __float2half_rn(v);
    l = __float2half_rn(v - __half2float(h));
}
__device__ __forceinline__ float sigm(float x) { return 1.f / (1.f + expf(-x)); }

#if TC_OK
__device__ __forceinline__ void cp16(uint32_t d, const void* g) {
    asm volatile("cp.async.cg.shared.global [%0], [%1], 16;" :: "r"(d), "l"(g));
}
__device__ __forceinline__ uint64_t sdesc(uint32_t a) {
    return 0x4000404000010000ull | ((uint64_t)(a >> 4) & 0x3FFFull);
}
__device__ __forceinline__ void mma_f16(uint32_t d, uint64_t ad, uint64_t bd, uint32_t en) {
    asm volatile(
        "{\n\t.reg .pred p;\n\t"
        "setp.ne.u32 p, %5, 0;\n\t"
        "tcgen05.mma.cta_group::1.kind::f16 [%0], %1, %2, %3, {%4, %4, %4, %4}, p;\n\t}"
        :: "r"(d), "l"(ad), "l"(bd), "r"(IDESC_F16), "r"(0u), "r"(en) : "memory");
}
__device__ __forceinline__ void mma_commit(uint32_t mb) {
    asm volatile("tcgen05.commit.cta_group::1.mbarrier::arrive::one.shared::cluster.b64 [%0];"
                 :: "r"(mb) : "memory");
}
__device__ __forceinline__ void mbar_init(uint32_t mb, uint32_t cnt) {
    asm volatile("mbarrier.init.shared.b64 [%0], %1;" :: "r"(mb), "r"(cnt) : "memory");
}
__device__ __forceinline__ void mbar_wait(uint32_t mb, uint32_t par) {
    asm volatile(
        "{\n\t.reg .pred P;\nW%=:\n\t"
        "mbarrier.try_wait.parity.shared.b64 P, [%0], %1;\n\t"
        "@!P bra W%=;\n\t}"
        :: "r"(mb), "r"(par) : "memory");
}
__device__ __forceinline__ void ldtm32(uint32_t* r, uint32_t a) {
    asm volatile(
        "tcgen05.ld.sync.aligned.32x32b.x32.b32 "
        "{%0,%1,%2,%3,%4,%5,%6,%7,%8,%9,%10,%11,%12,%13,%14,%15,"
        "%16,%17,%18,%19,%20,%21,%22,%23,%24,%25,%26,%27,%28,%29,%30,%31}, [%32];"
        : "=r"(r[0]),"=r"(r[1]),"=r"(r[2]),"=r"(r[3]),"=r"(r[4]),"=r"(r[5]),"=r"(r[6]),"=r"(r[7]),
          "=r"(r[8]),"=r"(r[9]),"=r"(r[10]),"=r"(r[11]),"=r"(r[12]),"=r"(r[13]),"=r"(r[14]),"=r"(r[15]),
          "=r"(r[16]),"=r"(r[17]),"=r"(r[18]),"=r"(r[19]),"=r"(r[20]),"=r"(r[21]),"=r"(r[22]),"=r"(r[23]),
          "=r"(r[24]),"=r"(r[25]),"=r"(r[26]),"=r"(r[27]),"=r"(r[28]),"=r"(r[29]),"=r"(r[30]),"=r"(r[31])
        : "r"(a));
}
#endif

// ---------------- GEMM: C[m,n] = sum_k A[m,k]*B[n,k]; A fp16 single, B fp16 hi/lo ----------------
// grid: x = M/128 (concurrent CTAs share the B panel in L2), y = N/128
// EPI: 0 fp32; 1 +bias relu -> fp16 single; 2 +bias fp32; 3 +addmat relu fp32;
//      4 Hebbian -> transposed fp16 hi/lo split
template<int EPI>
__global__ void __launch_bounds__(256, 1)
mma_gemm(const __half* __restrict__ A,
         const __half* __restrict__ Bh, const __half* __restrict__ Bl,
         int K, int ldC, float* __restrict__ C,
         const float* __restrict__ bias, const float* __restrict__ addmat,
         const float* __restrict__ Wold, const float* __restrict__ rmax,
         const float* __restrict__ rsum, const float* __restrict__ sdec,
         __half* __restrict__ Oh, __half* __restrict__ Ol) {
    extern __shared__ char dsm[];
    const int tid = threadIdx.x;
    const int m0 = blockIdx.x * 128, n0 = blockIdx.y * 128;

#if TC_OK
    __shared__ uint32_t s_tm;
    __shared__ __align__(8) uint64_t s_mb[NSTAGE];
    const int wid = tid >> 5, lid = tid & 31;
    uint32_t tile0 = (s2u(dsm) + 1023u) & ~1023u;
    uint32_t mbA[NSTAGE];
#pragma unroll
    for (int s = 0; s < NSTAGE; s++) mbA[s] = s2u(&s_mb[s]);

    if (wid == 0) {
        asm volatile("tcgen05.alloc.cta_group::1.sync.aligned.shared::cta.b32 [%0], %1;"
                     :: "r"(s2u(&s_tm)), "r"(128u) : "memory");
        asm volatile("tcgen05.relinquish_alloc_permit.cta_group::1.sync.aligned;");
    }
    if (tid == 0)
        for (int s = 0; s < NSTAGE; s++) mbar_init(mbA[s], 1);
    __syncthreads();
    const uint32_t tm = s_tm;

    const __half* srcs[3] = { A + (size_t)m0 * K, Bh + (size_t)n0 * K, Bl + (size_t)n0 * K };

    const int NC = K >> 6;

#define DO_COPY(i)                                                              \
    do {                                                                        \
        uint32_t base_ = tile0 + ((i) % NSTAGE) * STAGE_BYTES;                  \
        _Pragma("unroll")                                                       \
        for (int p = 0; p < 3; p++) {                                           \
            const __half* s_ = srcs[p] + (i) * 64;                              \
            uint32_t pb_ = base_ + p * 16384;                                   \
            _Pragma("unroll")                                                   \
            for (int t = 0; t < 4; t++) {                                       \
                int idx_ = tid + t * 256;                                       \
                int r_ = idx_ >> 3, c_ = idx_ & 7;                              \
                cp16(pb_ + sw128(r_ * 128 + c_ * 16), s_ + (size_t)r_ * K + c_ * 8); \
            }                                                                   \
        }                                                                       \
        asm volatile("cp.async.commit_group;" ::: "memory");                    \
    } while (0)

    // prologue: NSTAGE-1 copies in flight
    DO_COPY(0);
    if (NC > 1) DO_COPY(1);
    if (NC > 2) DO_COPY(2);

    for (int i = 0; i < NC; i++) {
        if (i + 3 < NC) {
            if (i >= 1) mbar_wait(mbA[(i - 1) % NSTAGE], ((i - 1) / NSTAGE) & 1);
            DO_COPY(i + 3);
        }
        if (i + 3 < NC)      asm volatile("cp.async.wait_group 3;" ::: "memory");
        else if (i + 2 < NC) asm volatile("cp.async.wait_group 2;" ::: "memory");
        else if (i + 1 < NC) asm volatile("cp.async.wait_group 1;" ::: "memory");
        else                 asm volatile("cp.async.wait_group 0;" ::: "memory");
        __syncthreads();
        if (tid == 0) {
            asm volatile("fence.proxy.async.shared::cta;" ::: "memory");
            uint32_t base = tile0 + (i % NSTAGE) * STAGE_BYTES;
            uint64_t ad = sdesc(base);
            uint64_t bh = sdesc(base + 16384), bl = sdesc(base + 32768);
#pragma unroll
            for (int s4 = 0; s4 < 4; s4++) {
                mma_f16(tm, ad + 2*s4, bh + 2*s4, (i > 0) | (s4 > 0));
                mma_f16(tm, ad + 2*s4, bl + 2*s4, 1);
            }
            mma_commit(mbA[i % NSTAGE]);
        }
    }
#undef DO_COPY

    for (int j = (NC >= NSTAGE ? NC - NSTAGE : 0); j < NC; j++)
        mbar_wait(mbA[j % NSTAGE], (j / NSTAGE) & 1);
    asm volatile("tcgen05.fence::after_thread_sync;" ::: "memory");

    if (wid < 4) {
        const int m = m0 + wid * 32 + lid;
        float sd = 0.f, rm = 0.f, irs = 1.f;
        if (EPI == 4) { sd = sdec[m]; rm = rmax[m]; irs = 1.f / rsum[m]; }
#pragma unroll
        for (int cb = 0; cb < 4; cb++) {
            uint32_t rr[32];
            ldtm32(rr, tm + cb * 32);
            asm volatile("tcgen05.wait::ld.sync.aligned;" ::: "memory");
            const int nb = n0 + cb * 32;
            if (EPI == 0) {
                float4* c4 = (float4*)(C + (size_t)m * ldC + nb);
#pragma unroll
                for (int q = 0; q < 8; q++)
                    c4[q] = make_float4(__uint_as_float(rr[4*q]), __uint_as_float(rr[4*q+1]),
                                        __uint_as_float(rr[4*q+2]), __uint_as_float(rr[4*q+3]));
            } else if (EPI == 1) {
#pragma unroll
                for (int j = 0; j < 32; j += 2) {
                    float v0 = fmaxf(__uint_as_float(rr[j])   + bias[nb+j],   0.f);
                    float v1 = fmaxf(__uint_as_float(rr[j+1]) + bias[nb+j+1], 0.f);
                    __half2 t = __floats2half2_rn(v0, v1);
                    *(__half2*)(Oh + (size_t)m * ldC + nb + j) = t;
                }
            } else if (EPI == 2) {
                float4* c4 = (float4*)(C + (size_t)m * ldC + nb);
#pragma unroll
                for (int q = 0; q < 8; q++)
                    c4[q] = make_float4(__uint_as_float(rr[4*q])   + bias[nb+4*q],
                                        __uint_as_float(rr[4*q+1]) + bias[nb+4*q+1],
                                        __uint_as_float(rr[4*q+2]) + bias[nb+4*q+2],
                                        __uint_as_float(rr[4*q+3]) + bias[nb+4*q+3]);
            } else if (EPI == 3) {
                const float4* a4 = (const float4*)(addmat + (size_t)m * ldC + nb);
                float4* c4 = (float4*)(C + (size_t)m * ldC + nb);
#pragma unroll
                for (int q = 0; q < 8; q++) {
                    float4 a = a4[q];
                    c4[q] = make_float4(fmaxf(__uint_as_float(rr[4*q])   + a.x, 0.f),
                                        fmaxf(__uint_as_float(rr[4*q+1]) + a.y, 0.f),
                                        fmaxf(__uint_as_float(rr[4*q+2]) + a.z, 0.f),
                                        fmaxf(__uint_as_float(rr[4*q+3]) + a.w, 0.f));
                }
            } else { // Hebbian: W_new = W + softmax(W)*corr/B - sd*W, stored transposed split
                const float4* w4 = (const float4*)(Wold + (size_t)m * D + nb);
#pragma unroll
                for (int q = 0; q < 8; q++) {
                    float4 w = w4[q];
                    float wv[4] = { w.x, w.y, w.z, w.w };
#pragma unroll
                    for (int e = 0; e < 4; e++) {
                        int j = 4*q + e;
                        float p = expf(wv[e] - rm) * irs;
                        float o = wv[e] + p * (__uint_as_float(rr[j]) * (1.0f/BB)) - sd * wv[e];
                        __half hh, ll;
                        split2h(o, hh, ll);
                        Oh[(size_t)(nb + j) * D + m] = hh;
                        Ol[(size_t)(nb + j) * D + m] = ll;
                    }
                }
            }
        }
    }
    __syncthreads();
    if (wid == 0)
        asm volatile("tcgen05.dealloc.cta_group::1.sync.aligned.b32 %0, %1;" :: "r"(tm), "r"(128u));

#else  // ---------- generic-target fallback ----------
    float* As = (float*)dsm;
    float* Bs = As + 16 * 132;
    const int tx = tid & 15, ty = tid >> 4;
    float acc[8][8];
#pragma unroll
    for (int i = 0; i < 8; i++)
#pragma unroll
        for (int j = 0; j < 8; j++) acc[i][j] = 0.f;

    for (int k0 = 0; k0 < K; k0 += 16) {
#pragma unroll
        for (int e = 0; e < 8; e++) {
            int idx = tid + e * 256;
            int r = idx >> 4, k = idx & 15;
            size_t ai = (size_t)(m0 + r) * K + k0 + k;
            size_t bi = (size_t)(n0 + r) * K + k0 + k;
            As[k * 132 + r] = __half2float(A[ai]);
            Bs[k * 132 + r] = __half2float(Bh[bi]) + __half2float(Bl[bi]);
        }
        __syncthreads();
#pragma unroll
        for (int kk = 0; kk < 16; kk++) {
            float a[8], b[8];
#pragma unroll
            for (int i = 0; i < 8; i++) a[i] = As[kk * 132 + ty * 8 + i];
#pragma unroll
            for (int j = 0; j < 8; j++) b[j] = Bs[kk * 132 + tx * 8 + j];
#pragma unroll
            for (int i = 0; i < 8; i++)
#pragma unroll
                for (int j = 0; j < 8; j++) acc[i][j] = fmaf(a[i], b[j], acc[i][j]);
        }
        __syncthreads();
    }
#pragma unroll
    for (int i = 0; i < 8; i++) {
        int m = m0 + ty * 8 + i;
        float sd = 0.f, rm = 0.f, irs = 1.f;
        if (EPI == 4) { sd = sdec[m]; rm = rmax[m]; irs = 1.f / rsum[m]; }
#pragma unroll
        for (int j = 0; j < 8; j++) {
            int n = n0 + tx * 8 + j;
            float v = acc[i][j];
            if (EPI == 0) C[(size_t)m * ldC + n] = v;
            else if (EPI == 1) Oh[(size_t)m * ldC + n] = __float2half_rn(fmaxf(v + bias[n], 0.f));
            else if (EPI == 2) C[(size_t)m * ldC + n] = v + bias[n];
            else if (EPI == 3) C[(size_t)m * ldC + n] = fmaxf(v + addmat[(size_t)m * ldC + n], 0.f);
            else {
                float w = Wold[(size_t)m * D + n];
                float p = expf(w - rm) * irs;
                float o = w + p * (v * (1.0f/BB)) - sd * w;
                __half hh, ll; split2h(o, hh, ll);
                Oh[(size_t)n * D + m] = hh; Ol[(size_t)n * D + m] = ll;
            }
        }
    }
#endif
}

// ---------------- block reduce + elementwise ----------------
__device__ __forceinline__ float blk_reduce(float v, bool do_max) {
    __shared__ float sh[32];
    int lane = threadIdx.x & 31, w = threadIdx.x >> 5;
#pragma unroll
    for (int o = 16; o; o >>= 1) {
        float t = __shfl_xor_sync(0xffffffffu, v, o);
        v = do_max ? fmaxf(v, t) : v + t;
    }
    if (lane == 0) sh[w] = v;
    __syncthreads();
    if (w == 0) {
        v = (lane < (int)(blockDim.x >> 5)) ? sh[lane] : (do_max ? -INFINITY : 0.f);
#pragma unroll
        for (int o = 16; o; o >>= 1) {
            float t = __shfl_xor_sync(0xffffffffu, v, o);
            v = do_max ? fmaxf(v, t) : v + t;
        }
        if (lane == 0) sh[0] = v;
    }
    __syncthreads();
    float r = sh[0];
    __syncthreads();
    return r;
}

// softmax of row -> transposed fp16 single [D, BB]
__global__ void row_softmax_t(const float* __restrict__ src, __half* __restrict__ dst) {
    int row = blockIdx.x;
    const float* x = src + (size_t)row * D;
    float m = -INFINITY;
    for (int i = threadIdx.x; i < D; i += blockDim.x) m = fmaxf(m, x[i]);
    m = blk_reduce(m, true);
    float s = 0.f;
    for (int i = threadIdx.x; i < D; i += blockDim.x) s += expf(x[i] - m);
    s = blk_reduce(s, false);
    float inv = 1.f / s;
    for (int i = threadIdx.x; i < D; i += blockDim.x)
        dst[(size_t)i * BB + row] = __float2half_rn(expf(x[i] - m) * inv);
}

__global__ void row_stats_kernel(const float* __restrict__ Wsrc,
                                 float* __restrict__ rmax, float* __restrict__ rsum) {
    int row = blockIdx.x;
    const float* x = Wsrc + (size_t)row * D;
    float m = -INFINITY;
    for (int i = threadIdx.x; i < D; i += blockDim.x) m = fmaxf(m, x[i]);
    m = blk_reduce(m, true);
    float s = 0.f;
    for (int i = threadIdx.x; i < D; i += blockDim.x) s += expf(x[i] - m);
    s = blk_reduce(s, false);
    if (threadIdx.x == 0) { rmax[row] = m; rsum[row] = s; }
}

__global__ void layernorm_kernel(const float* __restrict__ src,
                                 const float* __restrict__ g, const float* __restrict__ b,
                                 float* __restrict__ dst) {
    int row = blockIdx.x;
    const float* x = src + (size_t)row * D;
    float s = 0.f, s2 = 0.f;
    for (int i = threadIdx.x; i < D; i += blockDim.x) { float v = x[i]; s += v; s2 += v * v; }
    s = blk_reduce(s, false);
    s2 = blk_reduce(s2, false);
    float mean = s * (1.f / D);
    float rstd = rsqrtf(s2 * (1.f / D) - mean * mean + 1e-5f);
    for (int i = threadIdx.x; i < D; i += blockDim.x)
        dst[(size_t)row * D + i] = (x[i] - mean) * rstd * g[i] + b[i];
}

__global__ void zero_kernel(float* p, int n) {
    int i = blockIdx.x * blockDim.x + threadIdx.x;
    if (i < n) p[i] = 0.f;
}

__global__ void neuromod_partial(const float* __restrict__ nt,
                                 const float* __restrict__ dopamine,
                                 const float* __restrict__ serotonin,
                                 const float* __restrict__ gaba,
                                 const float* __restrict__ alpha,
                                 __half* __restrict__ maTh,
                                 __half* __restrict__ maTl,
                                 float* __restrict__ gsum) {
    int j = blockIdx.x * blockDim.x + threadIdx.x;
    int b0 = blockIdx.y * (BB / 8);
    float a = alpha[j];
    float gs = 0.f;
    for (int b = b0; b < b0 + BB / 8; b++) {
        const float* p = nt + (size_t)b * N3 + 3 * j;
        float pd = p[0], ps = p[1], pg = p[2];
        float inv = 1.f / fmaxf(ps, 1e-6f);
        size_t bi = (size_t)b * D + j;
        float dop = tanhf(dopamine[bi] + pd * inv);
        float ser = sigm(serotonin[bi] + ps);
        gs += sigm(gaba[bi] + pg * inv);
        __half h, l;
        split2h(a * dop * ser, h, l);
        maTh[(size_t)j * BB + b] = h;
        maTl[(size_t)j * BB + b] = l;
    }
    atomicAdd(&gsum[j], gs);
}

__global__ void sdecay_kernel(const float* __restrict__ gsum,
                              const float* __restrict__ decay, float* __restrict__ sdec) {
    int j = blockIdx.x * blockDim.x + threadIdx.x;
    sdec[j] = decay[j] * sigm(gsum[j] * (1.f / BB));
}

// fp32 -> fp16 single convert
__global__ void cvt_kernel(const float4* __restrict__ src, __half* __restrict__ dst, size_t n4) {
    size_t i = (size_t)blockIdx.x * blockDim.x + threadIdx.x;
    if (i >= n4) return;
    float4 v = src[i];
    ((__half2*)dst)[2*i]   = __floats2half2_rn(v.x, v.y);
    ((__half2*)dst)[2*i+1] = __floats2half2_rn(v.z, v.w);
}

// fp32 -> fp16 hi/lo split
__global__ void split_kernel(const float4* __restrict__ src,
                             __half* __restrict__ dh, __half* __restrict__ dl, size_t n4) {
    size_t i = (size_t)blockIdx.x * blockDim.x + threadIdx.x;
    if (i >= n4) return;
    float4 v = src[i];
    __half2 h0, h1, l0, l1;
    split2h(v.x, h0.x, l0.x); split2h(v.y, h0.y, l0.y);
    split2h(v.z, h1.x, l1.x); split2h(v.w, h1.y, l1.y);
    ((__half2*)dh)[2*i]   = h0; ((__half2*)dh)[2*i+1] = h1;
    ((__half2*)dl)[2*i]   = l0; ((__half2*)dl)[2*i+1] = l1;
}

// ---------------- host ----------------
template<typename T>
static void* sym_addr(T& sym) { void* p = nullptr; cudaGetSymbolAddress(&p, sym); return p; }
#define HF(sym) ((__half*)sym_addr(sym))
#define FP(sym) ((float*)sym_addr(sym))

extern "C" void kernel_launch(void* const* d_in, const int* in_sizes, int n_in,
                              void* d_out, int out_size) {
    const float* x        = (const float*)d_in[0];
    const float* prev_act = (const float*)d_in[1];
    const float* prev_rec = (const float*)d_in[2];
    const float* dopamine = (const float*)d_in[3];
    const float* serotonin= (const float*)d_in[4];
    const float* gaba     = (const float*)d_in[5];
    const float* W        = (const float*)d_in[6];
    const float* Wr       = (const float*)d_in[7];
    const float* alpha    = (const float*)d_in[8];
    const float* decay    = (const float*)d_in[9];
    const float* gact     = (const float*)d_in[10];
    const float* bact     = (const float*)d_in[11];
    const float* grec     = (const float*)d_in[12];
    const float* brec     = (const float*)d_in[13];
    const float* p1w      = (const float*)d_in[14];
    const float* p1b      = (const float*)d_in[15];
    const float* p2w      = (const float*)d_in[16];
    const float* p2b      = (const float*)d_in[17];
    float* out = (float*)d_out;

    cudaFuncSetAttribute(mma_gemm<0>, cudaFuncAttributeMaxDynamicSharedMemorySize, SMEM_BYTES);
    cudaFuncSetAttribute(mma_gemm<1>, cudaFuncAttributeMaxDynamicSharedMemorySize, SMEM_BYTES);
    cudaFuncSetAttribute(mma_gemm<2>, cudaFuncAttributeMaxDynamicSharedMemorySize, SMEM_BYTES);
    cudaFuncSetAttribute(mma_gemm<3>, cudaFuncAttributeMaxDynamicSharedMemorySize, SMEM_BYTES);
    cudaFuncSetAttribute(mma_gemm<4>, cudaFuncAttributeMaxDynamicSharedMemorySize, SMEM_BYTES);

    // converts / splits
    cvt_kernel<<<(BB*D/4 + 255)/256, 256>>>((const float4*)prev_act, HF(g_pa), BB*D/4);
    cvt_kernel<<<(BB*D/4 + 255)/256, 256>>>((const float4*)x,        HF(g_x),  BB*D/4);
    split_kernel<<<((size_t)D*D/4 + 255)/256, 256>>>((const float4*)p1w, HF(g_p1_h), HF(g_p1_l), (size_t)D*D/4);
    split_kernel<<<((size_t)N3*D/4 + 255)/256, 256>>>((const float4*)p2w, HF(g_p2_h), HF(g_p2_l), (size_t)N3*D/4);

    // softmaxes (transposed fp16) + W row stats
    row_softmax_t<<<BB, 256>>>(prev_act, HF(g_asT));
    row_softmax_t<<<BB, 256>>>(prev_rec, HF(g_arsT));
    row_stats_kernel<<<D, 256>>>(W,  FP(g_rmW), FP(g_rsW));
    row_stats_kernel<<<D, 256>>>(Wr, FP(g_rmR), FP(g_rsR));

    // h = relu(pa @ p1w^T + p1b) -> fp16 single
    mma_gemm<1><<<dim3(BB/128, D/128), 256, SMEM_BYTES>>>(
        HF(g_pa), HF(g_p1_h), HF(g_p1_l), D, D,
        nullptr, p1b, nullptr, nullptr, nullptr, nullptr, nullptr, HF(g_h), nullptr);
    // nt = h @ p2w^T + p2b  (fp32)
    mma_gemm<2><<<dim3(BB/128, N3/128), 256, SMEM_BYTES>>>(
        HF(g_h), HF(g_p2_h), HF(g_p2_l), D, N3,
        FP(g_nt), p2b, nullptr, nullptr, nullptr, nullptr, nullptr, nullptr, nullptr);

    // neuromodulators
    zero_kernel<<<D/256, 256>>>(FP(g_gsum), D);
    neuromod_partial<<<dim3(D/256, 8), 256>>>(FP(g_nt), dopamine, serotonin, gaba, alpha,
                                              HF(g_maT_h), HF(g_maT_l), FP(g_gsum));
    sdecay_kernel<<<D/256, 256>>>(FP(g_gsum), decay, FP(g_sdec));

    // Hebbian: W_new^T / Wr_new^T  (K = BB = 512)
    mma_gemm<4><<<dim3(D/128, D/128), 256, SMEM_BYTES>>>(
        HF(g_asT), HF(g_maT_h), HF(g_maT_l), BB, D,
        nullptr, nullptr, nullptr, W,  FP(g_rmW), FP(g_rsW), FP(g_sdec), HF(g_WnT_h), HF(g_WnT_l));
    mma_gemm<4><<<dim3(D/128, D/128), 256, SMEM_BYTES>>>(
        HF(g_arsT), HF(g_maT_h), HF(g_maT_l), BB, D,
        nullptr, nullptr, nullptr, Wr, FP(g_rmR), FP(g_rsR), FP(g_sdec), HF(g_WrT_h), HF(g_WrT_l));

    // rec = pa @ Wr_new ; recin = LN(rec)
    mma_gemm<0><<<dim3(BB/128, D/128), 256, SMEM_BYTES>>>(
        HF(g_pa), HF(g_WrT_h), HF(g_WrT_l), D, D,
        FP(g_rec), nullptr, nullptr, nullptr, nullptr, nullptr, nullptr, nullptr, nullptr);
    layernorm_kernel<<<BB, 256>>>(FP(g_rec), grec, brec, FP(g_recin));

    // act = relu(x @ W_new + recin) ; out = LN(act)
    mma_gemm<3><<<dim3(BB/128, D/128), 256, SMEM_BYTES>>>(
        HF(g_x), HF(g_WnT_h), HF(g_WnT_l), D, D,
        FP(g_act), nullptr, FP(g_recin), nullptr, nullptr, nullptr, nullptr, nullptr, nullptr);
    layernorm_kernel<<<BB, 256>>>(FP(g_act), gact, bact, out);
}

// round 7
// speedup vs baseline: 13.6473x; 1.1587x over previous
#include <cuda_runtime.h>
#include <cuda_fp16.h>
#include <math.h>
#include <stdint.h>

#define D 4096
#define BB 512
#define N3 (3*D)
#define NSTAGE 4
// kind::f16, fp16 inputs, fp32 accum, M=128, N=128
#define IDESC_F16 ((1u<<4)|(16u<<17)|(8u<<24))

#if defined(__CUDA_ARCH_FEAT_SM103_ALL) || defined(__CUDA_ARCH_FEAT_SM100_ALL) || \
    defined(__CUDA_ARCH_FEAT_SM101_ALL) || \
    (defined(__CUDA_ARCH_SPECIFIC__) && (__CUDA_ARCH_SPECIFIC__ >= 1000)) || \
    (defined(__CUDA_ARCH_FAMILY_SPECIFIC__) && (__CUDA_ARCH_FAMILY_SPECIFIC__ >= 1000))
#define TC_OK 1
#else
#define TC_OK 0
#endif

// ---------------- device scratch ----------------
__device__ __half g_pa[BB*D], g_x[BB*D], g_h[BB*D];
__device__ __half g_p1[(size_t)D*D];
__device__ __half g_p2[(size_t)N3*D];          // channel-permuted rows: c*D+j <- 3j+c
__device__ float  g_p2b[N3];                   // permuted bias
__device__ __half g_asT[(size_t)D*BB], g_arsT[(size_t)D*BB];
__device__ __half g_maT[(size_t)D*BB];
__device__ __half g_WnT_h[(size_t)D*D], g_WnT_l[(size_t)D*D];
__device__ __half g_WrT_h[(size_t)D*D], g_WrT_l[(size_t)D*D];
__device__ float g_nt[(size_t)BB*N3];
__device__ float g_rec[BB*D], g_recin[BB*D], g_act[BB*D];
__device__ float g_gsum[D], g_sdec[D], g_rmW[D], g_rsW[D], g_rmR[D], g_rsR[D];

// ---------------- helpers ----------------
__device__ __forceinline__ uint32_t s2u(const void* p) {
    uint32_t a;
    asm("{ .reg .u64 t; cvta.to.shared.u64 t, %1; cvt.u32.u64 %0, t; }" : "=r"(a) : "l"(p));
    return a;
}
__device__ __forceinline__ uint32_t sw128(uint32_t o) { return o ^ ((o >> 3) & 0x70); }
__device__ __forceinline__ void split2h(float v, __half& h, __half& l) {
    h = __float2half_rn(v);
    l = __float2half_rn(v - __half2float(h));
}
__device__ __forceinline__ float sigm(float x) { return 1.f / (1.f + expf(-x)); }

#if TC_OK
__device__ __forceinline__ void cp16(uint32_t d, const void* g) {
    asm volatile("cp.async.cg.shared.global [%0], [%1], 16;" :: "r"(d), "l"(g));
}
__device__ __forceinline__ uint64_t sdesc(uint32_t a) {
    return 0x4000404000010000ull | ((uint64_t)(a >> 4) & 0x3FFFull);
}
__device__ __forceinline__ void mma_f16(uint32_t d, uint64_t ad, uint64_t bd, uint32_t en) {
    asm volatile(
        "{\n\t.reg .pred p;\n\t"
        "setp.ne.u32 p, %5, 0;\n\t"
        "tcgen05.mma.cta_group::1.kind::f16 [%0], %1, %2, %3, {%4, %4, %4, %4}, p;\n\t}"
        :: "r"(d), "l"(ad), "l"(bd), "r"(IDESC_F16), "r"(0u), "r"(en) : "memory");
}
__device__ __forceinline__ void mma_commit(uint32_t mb) {
    asm volatile("tcgen05.commit.cta_group::1.mbarrier::arrive::one.shared::cluster.b64 [%0];"
                 :: "r"(mb) : "memory");
}
__device__ __forceinline__ void mbar_init(uint32_t mb, uint32_t cnt) {
    asm volatile("mbarrier.init.shared.b64 [%0], %1;" :: "r"(mb), "r"(cnt) : "memory");
}
__device__ __forceinline__ void mbar_wait(uint32_t mb, uint32_t par) {
    asm volatile(
        "{\n\t.reg .pred P;\nW%=:\n\t"
        "mbarrier.try_wait.parity.shared.b64 P, [%0], %1;\n\t"
        "@!P bra W%=;\n\t}"
        :: "r"(mb), "r"(par) : "memory");
}
__device__ __forceinline__ void ldtm32(uint32_t* r, uint32_t a) {
    asm volatile(
        "tcgen05.ld.sync.aligned.32x32b.x32.b32 "
        "{%0,%1,%2,%3,%4,%5,%6,%7,%8,%9,%10,%11,%12,%13,%14,%15,"
        "%16,%17,%18,%19,%20,%21,%22,%23,%24,%25,%26,%27,%28,%29,%30,%31}, [%32];"
        : "=r"(r[0]),"=r"(r[1]),"=r"(r[2]),"=r"(r[3]),"=r"(r[4]),"=r"(r[5]),"=r"(r[6]),"=r"(r[7]),
          "=r"(r[8]),"=r"(r[9]),"=r"(r[10]),"=r"(r[11]),"=r"(r[12]),"=r"(r[13]),"=r"(r[14]),"=r"(r[15]),
          "=r"(r[16]),"=r"(r[17]),"=r"(r[18]),"=r"(r[19]),"=r"(r[20]),"=r"(r[21]),"=r"(r[22]),"=r"(r[23]),
          "=r"(r[24]),"=r"(r[25]),"=r"(r[26]),"=r"(r[27]),"=r"(r[28]),"=r"(r[29]),"=r"(r[30]),"=r"(r[31])
        : "r"(a));
}
#endif

// ---------------- GEMM: C[m,n] = sum_k A[m,k]*B[n,k]; A fp16 single; B = NBL fp16 panels ----------------
// grid: x = M/128 (concurrent CTAs share B panel in L2), y = N/128
// EPI: 0 fp32; 1 +bias relu -> fp16; 2 +bias fp32; 3 +addmat relu fp32; 4 Hebbian -> transposed hi/lo
template<int EPI, int NBL>
__global__ void __launch_bounds__(256, 1)
mma_gemm(const __half* __restrict__ A,
         const __half* __restrict__ Bh, const __half* __restrict__ Bl,
         int K, int ldC, float* __restrict__ C,
         const float* __restrict__ bias, const float* __restrict__ addmat,
         const float* __restrict__ Wold, const float* __restrict__ rmax,
         const float* __restrict__ rsum, const float* __restrict__ sdec,
         __half* __restrict__ Oh, __half* __restrict__ Ol) {
    extern __shared__ char dsm[];
    const int tid = threadIdx.x;
    const int m0 = blockIdx.x * 128, n0 = blockIdx.y * 128;
    constexpr int NP = 1 + NBL;                 // panels per stage
    constexpr int STAGE = NP * 16384;

#if TC_OK
    __shared__ uint32_t s_tm;
    __shared__ __align__(8) uint64_t s_mb[NSTAGE];
    const int wid = tid >> 5, lid = tid & 31;
    uint32_t tile0 = (s2u(dsm) + 1023u) & ~1023u;
    uint32_t mbA[NSTAGE];
#pragma unroll
    for (int s = 0; s < NSTAGE; s++) mbA[s] = s2u(&s_mb[s]);

    if (wid == 0) {
        asm volatile("tcgen05.alloc.cta_group::1.sync.aligned.shared::cta.b32 [%0], %1;"
                     :: "r"(s2u(&s_tm)), "r"(128u) : "memory");
        asm volatile("tcgen05.relinquish_alloc_permit.cta_group::1.sync.aligned;");
    }
    if (tid == 0)
        for (int s = 0; s < NSTAGE; s++) mbar_init(mbA[s], 1);
    __syncthreads();
    const uint32_t tm = s_tm;

    const __half* srcs[3] = { A + (size_t)m0 * K, Bh + (size_t)n0 * K,
                              NBL == 2 ? Bl + (size_t)n0 * K : nullptr };

    const int NC = K >> 6;

#define DO_COPY(i)                                                              \
    do {                                                                        \
        uint32_t base_ = tile0 + ((i) % NSTAGE) * STAGE;                        \
        _Pragma("unroll")                                                       \
        for (int p = 0; p < NP; p++) {                                          \
            const __half* s_ = srcs[p] + (i) * 64;                              \
            uint32_t pb_ = base_ + p * 16384;                                   \
            _Pragma("unroll")                                                   \
            for (int t = 0; t < 4; t++) {                                       \
                int idx_ = tid + t * 256;                                       \
                int r_ = idx_ >> 3, c_ = idx_ & 7;                              \
                cp16(pb_ + sw128(r_ * 128 + c_ * 16), s_ + (size_t)r_ * K + c_ * 8); \
            }                                                                   \
        }                                                                       \
        asm volatile("cp.async.commit_group;" ::: "memory");                    \
    } while (0)

    DO_COPY(0);
    if (NC > 1) DO_COPY(1);
    if (NC > 2) DO_COPY(2);

    for (int i = 0; i < NC; i++) {
        if (i + 3 < NC) {
            if (i >= 1) mbar_wait(mbA[(i - 1) % NSTAGE], ((i - 1) / NSTAGE) & 1);
            DO_COPY(i + 3);
        }
        if (i + 3 < NC)      asm volatile("cp.async.wait_group 3;" ::: "memory");
        else if (i + 2 < NC) asm volatile("cp.async.wait_group 2;" ::: "memory");
        else if (i + 1 < NC) asm volatile("cp.async.wait_group 1;" ::: "memory");
        else                 asm volatile("cp.async.wait_group 0;" ::: "memory");
        __syncthreads();
        if (tid == 0) {
            asm volatile("fence.proxy.async.shared::cta;" ::: "memory");
            uint32_t base = tile0 + (i % NSTAGE) * STAGE;
            uint64_t ad = sdesc(base);
            uint64_t bh = sdesc(base + 16384);
            uint64_t bl = sdesc(base + 32768);
#pragma unroll
            for (int s4 = 0; s4 < 4; s4++) {
                mma_f16(tm, ad + 2*s4, bh + 2*s4, (i > 0) | (s4 > 0));
                if (NBL == 2) mma_f16(tm, ad + 2*s4, bl + 2*s4, 1);
            }
            mma_commit(mbA[i % NSTAGE]);
        }
    }
#undef DO_COPY

    for (int j = (NC >= NSTAGE ? NC - NSTAGE : 0); j < NC; j++)
        mbar_wait(mbA[j % NSTAGE], (j / NSTAGE) & 1);
    asm volatile("tcgen05.fence::after_thread_sync;" ::: "memory");

    if (wid < 4) {
        const int m = m0 + wid * 32 + lid;
        float sd = 0.f, rm = 0.f, irs = 1.f;
        if (EPI == 4) { sd = sdec[m]; rm = rmax[m]; irs = 1.f / rsum[m]; }
#pragma unroll
        for (int cb = 0; cb < 4; cb++) {
            uint32_t rr[32];
            ldtm32(rr, tm + cb * 32);
            asm volatile("tcgen05.wait::ld.sync.aligned;" ::: "memory");
            const int nb = n0 + cb * 32;
            if (EPI == 0) {
                float4* c4 = (float4*)(C + (size_t)m * ldC + nb);
#pragma unroll
                for (int q = 0; q < 8; q++)
                    c4[q] = make_float4(__uint_as_float(rr[4*q]), __uint_as_float(rr[4*q+1]),
                                        __uint_as_float(rr[4*q+2]), __uint_as_float(rr[4*q+3]));
            } else if (EPI == 1) {
#pragma unroll
                for (int j = 0; j < 32; j += 2) {
                    float v0 = fmaxf(__uint_as_float(rr[j])   + bias[nb+j],   0.f);
                    float v1 = fmaxf(__uint_as_float(rr[j+1]) + bias[nb+j+1], 0.f);
                    *(__half2*)(Oh + (size_t)m * ldC + nb + j) = __floats2half2_rn(v0, v1);
                }
            } else if (EPI == 2) {
                float4* c4 = (float4*)(C + (size_t)m * ldC + nb);
#pragma unroll
                for (int q = 0; q < 8; q++)
                    c4[q] = make_float4(__uint_as_float(rr[4*q])   + bias[nb+4*q],
                                        __uint_as_float(rr[4*q+1]) + bias[nb+4*q+1],
                                        __uint_as_float(rr[4*q+2]) + bias[nb+4*q+2],
                                        __uint_as_float(rr[4*q+3]) + bias[nb+4*q+3]);
            } else if (EPI == 3) {
                const float4* a4 = (const float4*)(addmat + (size_t)m * ldC + nb);
                float4* c4 = (float4*)(C + (size_t)m * ldC + nb);
#pragma unroll
                for (int q = 0; q < 8; q++) {
                    float4 a = a4[q];
                    c4[q] = make_float4(fmaxf(__uint_as_float(rr[4*q])   + a.x, 0.f),
                                        fmaxf(__uint_as_float(rr[4*q+1]) + a.y, 0.f),
                                        fmaxf(__uint_as_float(rr[4*q+2]) + a.z, 0.f),
                                        fmaxf(__uint_as_float(rr[4*q+3]) + a.w, 0.f));
                }
            } else { // Hebbian: W_new = W + softmax(W)*corr/B - sd*W, transposed hi/lo
                const float4* w4 = (const float4*)(Wold + (size_t)m * D + nb);
#pragma unroll
                for (int q = 0; q < 8; q++) {
                    float4 w = w4[q];
                    float wv[4] = { w.x, w.y, w.z, w.w };
#pragma unroll
                    for (int e = 0; e < 4; e++) {
                        int j = 4*q + e;
                        float p = expf(wv[e] - rm) * irs;
                        float o = wv[e] + p * (__uint_as_float(rr[j]) * (1.0f/BB)) - sd * wv[e];
                        __half hh, ll;
                        split2h(o, hh, ll);
                        Oh[(size_t)(nb + j) * D + m] = hh;
                        Ol[(size_t)(nb + j) * D + m] = ll;
                    }
                }
            }
        }
    }
    __syncthreads();
    if (wid == 0)
        asm volatile("tcgen05.dealloc.cta_group::1.sync.aligned.b32 %0, %1;" :: "r"(tm), "r"(128u));

#else  // ---------- generic-target fallback ----------
    float* As = (float*)dsm;
    float* Bs = As + 16 * 132;
    const int tx = tid & 15, ty = tid >> 4;
    float acc[8][8];
#pragma unroll
    for (int i = 0; i < 8; i++)
#pragma unroll
        for (int j = 0; j < 8; j++) acc[i][j] = 0.f;

    for (int k0 = 0; k0 < K; k0 += 16) {
#pragma unroll
        for (int e = 0; e < 8; e++) {
            int idx = tid + e * 256;
            int r = idx >> 4, k = idx & 15;
            size_t ai = (size_t)(m0 + r) * K + k0 + k;
            size_t bi = (size_t)(n0 + r) * K + k0 + k;
            As[k * 132 + r] = __half2float(A[ai]);
            float bv = __half2float(Bh[bi]);
            if (NBL == 2) bv += __half2float(Bl[bi]);
            Bs[k * 132 + r] = bv;
        }
        __syncthreads();
#pragma unroll
        for (int kk = 0; kk < 16; kk++) {
            float a[8], b[8];
#pragma unroll
            for (int i = 0; i < 8; i++) a[i] = As[kk * 132 + ty * 8 + i];
#pragma unroll
            for (int j = 0; j < 8; j++) b[j] = Bs[kk * 132 + tx * 8 + j];
#pragma unroll
            for (int i = 0; i < 8; i++)
#pragma unroll
                for (int j = 0; j < 8; j++) acc[i][j] = fmaf(a[i], b[j], acc[i][j]);
        }
        __syncthreads();
    }
#pragma unroll
    for (int i = 0; i < 8; i++) {
        int m = m0 + ty * 8 + i;
        float sd = 0.f, rm = 0.f, irs = 1.f;
        if (EPI == 4) { sd = sdec[m]; rm = rmax[m]; irs = 1.f / rsum[m]; }
#pragma unroll
        for (int j = 0; j < 8; j++) {
            int n = n0 + tx * 8 + j;
            float v = acc[i][j];
            if (EPI == 0) C[(size_t)m * ldC + n] = v;
            else if (EPI == 1) Oh[(size_t)m * ldC + n] = __float2half_rn(fmaxf(v + bias[n], 0.f));
            else if (EPI == 2) C[(size_t)m * ldC + n] = v + bias[n];
            else if (EPI == 3) C[(size_t)m * ldC + n] = fmaxf(v + addmat[(size_t)m * ldC + n], 0.f);
            else {
                float w = Wold[(size_t)m * D + n];
                float p = expf(w - rm) * irs;
                float o = w + p * (v * (1.0f/BB)) - sd * w;
                __half hh, ll; split2h(o, hh, ll);
                Oh[(size_t)n * D + m] = hh; Ol[(size_t)n * D + m] = ll;
            }
        }
    }
#endif
}

// ---------------- block reduce + elementwise ----------------
__device__ __forceinline__ float blk_reduce(float v, bool do_max) {
    __shared__ float sh[32];
    int lane = threadIdx.x & 31, w = threadIdx.x >> 5;
#pragma unroll
    for (int o = 16; o; o >>= 1) {
        float t = __shfl_xor_sync(0xffffffffu, v, o);
        v = do_max ? fmaxf(v, t) : v + t;
    }
    if (lane == 0) sh[w] = v;
    __syncthreads();
    if (w == 0) {
        v = (lane < (int)(blockDim.x >> 5)) ? sh[lane] : (do_max ? -INFINITY : 0.f);
#pragma unroll
        for (int o = 16; o; o >>= 1) {
            float t = __shfl_xor_sync(0xffffffffu, v, o);
            v = do_max ? fmaxf(v, t) : v + t;
        }
        if (lane == 0) sh[0] = v;
    }
    __syncthreads();
    float r = sh[0];
    __syncthreads();
    return r;
}

__global__ void row_softmax_t(const float* __restrict__ src, __half* __restrict__ dst) {
    int row = blockIdx.x;
    const float* x = src + (size_t)row * D;
    float m = -INFINITY;
    for (int i = threadIdx.x; i < D; i += blockDim.x) m = fmaxf(m, x[i]);
    m = blk_reduce(m, true);
    float s = 0.f;
    for (int i = threadIdx.x; i < D; i += blockDim.x) s += expf(x[i] - m);
    s = blk_reduce(s, false);
    float inv = 1.f / s;
    for (int i = threadIdx.x; i < D; i += blockDim.x)
        dst[(size_t)i * BB + row] = __float2half_rn(expf(x[i] - m) * inv);
}

__global__ void row_stats_kernel(const float* __restrict__ Wsrc,
                                 float* __restrict__ rmax, float* __restrict__ rsum) {
    int row = blockIdx.x;
    const float* x = Wsrc + (size_t)row * D;
    float m = -INFINITY;
    for (int i = threadIdx.x; i < D; i += blockDim.x) m = fmaxf(m, x[i]);
    m = blk_reduce(m, true);
    float s = 0.f;
    for (int i = threadIdx.x; i < D; i += blockDim.x) s += expf(x[i] - m);
    s = blk_reduce(s, false);
    if (threadIdx.x == 0) { rmax[row] = m; rsum[row] = s; }
}

__global__ void layernorm_kernel(const float* __restrict__ src,
                                 const float* __restrict__ g, const float* __restrict__ b,
                                 float* __restrict__ dst) {
    int row = blockIdx.x;
    const float* x = src + (size_t)row * D;
    float s = 0.f, s2 = 0.f;
    for (int i = threadIdx.x; i < D; i += blockDim.x) { float v = x[i]; s += v; s2 += v * v; }
    s = blk_reduce(s, false);
    s2 = blk_reduce(s2, false);
    float mean = s * (1.f / D);
    float rstd = rsqrtf(s2 * (1.f / D) - mean * mean + 1e-5f);
    for (int i = threadIdx.x; i < D; i += blockDim.x)
        dst[(size_t)row * D + i] = (x[i] - mean) * rstd * g[i] + b[i];
}

__global__ void zero_kernel(float* p, int n) {
    int i = blockIdx.x * blockDim.x + threadIdx.x;
    if (i < n) p[i] = 0.f;
}

// nt is channel-plane layout: nt[b, c*D + j]
__global__ void neuromod_partial(const float* __restrict__ nt,
                                 const float* __restrict__ dopamine,
                                 const float* __restrict__ serotonin,
                                 const float* __restrict__ gaba,
                                 const float* __restrict__ alpha,
                                 __half* __restrict__ maT,
                                 float* __restrict__ gsum) {
    int j = blockIdx.x * blockDim.x + threadIdx.x;
    int b0 = blockIdx.y * (BB / 8);
    float a = alpha[j];
    float gs = 0.f;
    for (int b = b0; b < b0 + BB / 8; b++) {
        const float* p = nt + (size_t)b * N3;
        float pd = p[j], ps = p[D + j], pg = p[2*D + j];
        float inv = 1.f / fmaxf(ps, 1e-6f);
        size_t bi = (size_t)b * D + j;
        float dop = tanhf(dopamine[bi] + pd * inv);
        float ser = sigm(serotonin[bi] + ps);
        gs += sigm(gaba[bi] + pg * inv);
        maT[(size_t)j * BB + b] = __float2half_rn(a * dop * ser);
    }
    atomicAdd(&gsum[j], gs);
}

__global__ void sdecay_kernel(const float* __restrict__ gsum,
                              const float* __restrict__ decay, float* __restrict__ sdec) {
    int j = blockIdx.x * blockDim.x + threadIdx.x;
    sdec[j] = decay[j] * sigm(gsum[j] * (1.f / BB));
}

// fp32 -> fp16 single convert
__global__ void cvt_kernel(const float4* __restrict__ src, __half* __restrict__ dst, size_t n4) {
    size_t i = (size_t)blockIdx.x * blockDim.x + threadIdx.x;
    if (i >= n4) return;
    float4 v = src[i];
    ((__half2*)dst)[2*i]   = __floats2half2_rn(v.x, v.y);
    ((__half2*)dst)[2*i+1] = __floats2half2_rn(v.z, v.w);
}

// p2w row 3j+c -> fp16 row c*D+j  (one block per source row)
__global__ void cvt_permute_kernel(const float* __restrict__ src, __half* __restrict__ dst) {
    int r = blockIdx.x;                 // 0..N3-1
    int c = r % 3, j = r / 3;
    const float4* s4 = (const float4*)(src + (size_t)r * D);
    __half2* d2 = (__half2*)(dst + (size_t)(c * D + j) * D);
    for (int i = threadIdx.x; i < D / 4; i += blockDim.x) {
        float4 v = s4[i];
        d2[2*i]   = __floats2half2_rn(v.x, v.y);
        d2[2*i+1] = __floats2half2_rn(v.z, v.w);
    }
}

__global__ void permute_bias_kernel(const float* __restrict__ src, float* __restrict__ dst) {
    int r = blockIdx.x * blockDim.x + threadIdx.x;
    if (r < N3) dst[(r % 3) * D + r / 3] = src[r];
}

// ---------------- host ----------------
template<typename T>
static void* sym_addr(T& sym) { void* p = nullptr; cudaGetSymbolAddress(&p, sym); return p; }
#define HF(sym) ((__half*)sym_addr(sym))
#define FP(sym) ((float*)sym_addr(sym))

extern "C" void kernel_launch(void* const* d_in, const int* in_sizes, int n_in,
                              void* d_out, int out_size) {
    const float* x        = (const float*)d_in[0];
    const float* prev_act = (const float*)d_in[1];
    const float* prev_rec = (const float*)d_in[2];
    const float* dopamine = (const float*)d_in[3];
    const float* serotonin= (const float*)d_in[4];
    const float* gaba     = (const float*)d_in[5];
    const float* W        = (const float*)d_in[6];
    const float* Wr       = (const float*)d_in[7];
    const float* alpha    = (const float*)d_in[8];
    const float* decay    = (const float*)d_in[9];
    const float* gact     = (const float*)d_in[10];
    const float* bact     = (const float*)d_in[11];
    const float* grec     = (const float*)d_in[12];
    const float* brec     = (const float*)d_in[13];
    const float* p1w      = (const float*)d_in[14];
    const float* p1b      = (const float*)d_in[15];
    const float* p2w      = (const float*)d_in[16];
    const float* p2b      = (const float*)d_in[17];
    float* out = (float*)d_out;

    const int SM1 = 2 * 16384 * NSTAGE + 1024;   // NBL=1 stages
    const int SM2 = 3 * 16384 * NSTAGE + 1024;   // NBL=2 stages
    cudaFuncSetAttribute((const void*)mma_gemm<1,1>, cudaFuncAttributeMaxDynamicSharedMemorySize, SM1);
    cudaFuncSetAttribute((const void*)mma_gemm<2,1>, cudaFuncAttributeMaxDynamicSharedMemorySize, SM1);
    cudaFuncSetAttribute((const void*)mma_gemm<4,1>, cudaFuncAttributeMaxDynamicSharedMemorySize, SM1);
    cudaFuncSetAttribute((const void*)mma_gemm<0,2>, cudaFuncAttributeMaxDynamicSharedMemorySize, SM2);
    cudaFuncSetAttribute((const void*)mma_gemm<3,2>, cudaFuncAttributeMaxDynamicSharedMemorySize, SM2);

    // converts
    cvt_kernel<<<(BB*D/4 + 255)/256, 256>>>((const float4*)prev_act, HF(g_pa), BB*D/4);
    cvt_kernel<<<(BB*D/4 + 255)/256, 256>>>((const float4*)x,        HF(g_x),  BB*D/4);
    cvt_kernel<<<((size_t)D*D/4 + 255)/256, 256>>>((const float4*)p1w, HF(g_p1), (size_t)D*D/4);
    cvt_permute_kernel<<<N3, 256>>>(p2w, HF(g_p2));
    permute_bias_kernel<<<(N3 + 255)/256, 256>>>(p2b, FP(g_p2b));

    // softmaxes (transposed fp16) + W row stats
    row_softmax_t<<<BB, 256>>>(prev_act, HF(g_asT));
    row_softmax_t<<<BB, 256>>>(prev_rec, HF(g_arsT));
    row_stats_kernel<<<D, 256>>>(W,  FP(g_rmW), FP(g_rsW));
    row_stats_kernel<<<D, 256>>>(Wr, FP(g_rmR), FP(g_rsR));

    // h = relu(pa @ p1w^T + p1b) -> fp16
    mma_gemm<1,1><<<dim3(BB/128, D/128), 256, SM1>>>(
        HF(g_pa), HF(g_p1), nullptr, D, D,
        nullptr, p1b, nullptr, nullptr, nullptr, nullptr, nullptr, HF(g_h), nullptr);
    // nt = h @ p2'^T + p2b'  (channel-plane layout, fp32)
    mma_gemm<2,1><<<dim3(BB/128, N3/128), 256, SM1>>>(
        HF(g_h), HF(g_p2), nullptr, D, N3,
        FP(g_nt), FP(g_p2b), nullptr, nullptr, nullptr, nullptr, nullptr, nullptr, nullptr);

    // neuromodulators
    zero_kernel<<<D/256, 256>>>(FP(g_gsum), D);
    neuromod_partial<<<dim3(D/256, 8), 256>>>(FP(g_nt), dopamine, serotonin, gaba, alpha,
                                              HF(g_maT), FP(g_gsum));
    sdecay_kernel<<<D/256, 256>>>(FP(g_gsum), decay, FP(g_sdec));

    // Hebbian: W_new^T / Wr_new^T (K = BB = 512)
    mma_gemm<4,1><<<dim3(D/128, D/128), 256, SM1>>>(
        HF(g_asT), HF(g_maT), nullptr, BB, D,
        nullptr, nullptr, nullptr, W,  FP(g_rmW), FP(g_rsW), FP(g_sdec), HF(g_WnT_h), HF(g_WnT_l));
    mma_gemm<4,1><<<dim3(D/128, D/128), 256, SM1>>>(
        HF(g_arsT), HF(g_maT), nullptr, BB, D,
        nullptr, nullptr, nullptr, Wr, FP(g_rmR), FP(g_rsR), FP(g_sdec), HF(g_WrT_h), HF(g_WrT_l));

    // rec = pa @ Wr_new ; recin = LN(rec)
    mma_gemm<0,2><<<dim3(BB/128, D/128), 256, SM2>>>(
        HF(g_pa), HF(g_WrT_h), HF(g_WrT_l), D, D,
        FP(g_rec), nullptr, nullptr, nullptr, nullptr, nullptr, nullptr, nullptr, nullptr);
    layernorm_kernel<<<BB, 256>>>(FP(g_rec), grec, brec, FP(g_recin));

    // act = relu(x @ W_new + recin) ; out = LN(act)
    mma_gemm<3,2><<<dim3(BB/128, D/128), 256, SM2>>>(
        HF(g_x), HF(g_WnT_h), HF(g_WnT_l), D, D,
        FP(g_act), nullptr, FP(g_recin), nullptr, nullptr, nullptr, nullptr, nullptr, nullptr);
    layernorm_kernel<<<BB, 256>>>(FP(g_act), gact, bact, out);
}

// round 9
// speedup vs baseline: 16.5976x; 1.2162x over previous
#include <cuda_runtime.h>
#include <cuda_fp16.h>
#include <math.h>
#include <stdint.h>

#define D 4096
#define BB 512
#define N3 (3*D)
// kind::f16, fp16 inputs, fp32 accum, M=128, N=128
#define IDESC_F16 ((1u<<4)|(16u<<17)|(8u<<24))

#if defined(__CUDA_ARCH_FEAT_SM103_ALL) || defined(__CUDA_ARCH_FEAT_SM100_ALL) || \
    defined(__CUDA_ARCH_FEAT_SM101_ALL) || \
    (defined(__CUDA_ARCH_SPECIFIC__) && (__CUDA_ARCH_SPECIFIC__ >= 1000)) || \
    (defined(__CUDA_ARCH_FAMILY_SPECIFIC__) && (__CUDA_ARCH_FAMILY_SPECIFIC__ >= 1000))
#define TC_OK 1
#else
#define TC_OK 0
#endif

// ---------------- device scratch ----------------
__device__ __half g_pa[BB*D], g_x[BB*D], g_h[BB*D];
__device__ __half g_p1[(size_t)D*D];
__device__ __half g_p2[(size_t)N3*D];          // channel-permuted rows: c*D+j <- 3j+c
__device__ float  g_p2b[N3];
__device__ __half g_asT[(size_t)D*BB], g_arsT[(size_t)D*BB];
__device__ __half g_maT[(size_t)D*BB];
__device__ __half g_WnT_h[(size_t)D*D], g_WnT_l[(size_t)D*D];
__device__ __half g_WrT_h[(size_t)D*D], g_WrT_l[(size_t)D*D];
__device__ float g_nt[(size_t)BB*N3];
__device__ float g_rec[BB*D], g_recin[BB*D], g_act[BB*D];
__device__ float g_gsum[D], g_sdec[D], g_rmW[D], g_rsW[D], g_rmR[D], g_rsR[D];
__device__ float g_mPA[BB], g_sPA[BB], g_mPR[BB], g_sPR[BB];

// ---------------- helpers ----------------
__device__ __forceinline__ uint32_t s2u(const void* p) {
    uint32_t a;
    asm("{ .reg .u64 t; cvta.to.shared.u64 t, %1; cvt.u32.u64 %0, t; }" : "=r"(a) : "l"(p));
    return a;
}
__device__ __forceinline__ uint32_t sw128(uint32_t o) { return o ^ ((o >> 3) & 0x70); }
__device__ __forceinline__ void split2h(float v, __half& h, __half& l) {
    h = __float2half_rn(v);
    l = __float2half_rn(v - __half2float(h));
}
__device__ __forceinline__ float sigm(float x) { return 1.f / (1.f + expf(-x)); }

#if TC_OK
__device__ __forceinline__ void cp16(uint32_t d, const void* g) {
    asm volatile("cp.async.cg.shared.global [%0], [%1], 16;" :: "r"(d), "l"(g));
}
template<int N> __device__ __forceinline__ void cp_wait() {
    asm volatile("cp.async.wait_group %0;" :: "n"(N) : "memory");
}
__device__ __forceinline__ void cp_wait_n(int n) {
    switch (n) {
        case 0: cp_wait<0>(); break; case 1: cp_wait<1>(); break;
        case 2: cp_wait<2>(); break; case 3: cp_wait<3>(); break;
        case 4: cp_wait<4>(); break; default: cp_wait<5>(); break;
    }
}
__device__ __forceinline__ uint64_t sdesc(uint32_t a) {
    return 0x4000404000010000ull | ((uint64_t)(a >> 4) & 0x3FFFull);
}
__device__ __forceinline__ void mma_f16(uint32_t d, uint64_t ad, uint64_t bd, uint32_t en) {
    asm volatile(
        "{\n\t.reg .pred p;\n\t"
        "setp.ne.u32 p, %5, 0;\n\t"
        "tcgen05.mma.cta_group::1.kind::f16 [%0], %1, %2, %3, {%4, %4, %4, %4}, p;\n\t}"
        :: "r"(d), "l"(ad), "l"(bd), "r"(IDESC_F16), "r"(0u), "r"(en) : "memory");
}
__device__ __forceinline__ void mma_commit(uint32_t mb) {
    asm volatile("tcgen05.commit.cta_group::1.mbarrier::arrive::one.shared::cluster.b64 [%0];"
                 :: "r"(mb) : "memory");
}
__device__ __forceinline__ void mbar_init(uint32_t mb, uint32_t cnt) {
    asm volatile("mbarrier.init.shared.b64 [%0], %1;" :: "r"(mb), "r"(cnt) : "memory");
}
__device__ __forceinline__ void mbar_wait(uint32_t mb, uint32_t par) {
    asm volatile(
        "{\n\t.reg .pred P;\nW%=:\n\t"
        "mbarrier.try_wait.parity.shared.b64 P, [%0], %1;\n\t"
        "@!P bra W%=;\n\t}"
        :: "r"(mb), "r"(par) : "memory");
}
__device__ __forceinline__ void ldtm32(uint32_t* r, uint32_t a) {
    asm volatile(
        "tcgen05.ld.sync.aligned.32x32b.x32.b32 "
        "{%0,%1,%2,%3,%4,%5,%6,%7,%8,%9,%10,%11,%12,%13,%14,%15,"
        "%16,%17,%18,%19,%20,%21,%22,%23,%24,%25,%26,%27,%28,%29,%30,%31}, [%32];"
        : "=r"(r[0]),"=r"(r[1]),"=r"(r[2]),"=r"(r[3]),"=r"(r[4]),"=r"(r[5]),"=r"(r[6]),"=r"(r[7]),
          "=r"(r[8]),"=r"(r[9]),"=r"(r[10]),"=r"(r[11]),"=r"(r[12]),"=r"(r[13]),"=r"(r[14]),"=r"(r[15]),
          "=r"(r[16]),"=r"(r[17]),"=r"(r[18]),"=r"(r[19]),"=r"(r[20]),"=r"(r[21]),"=r"(r[22]),"=r"(r[23]),
          "=r"(r[24]),"=r"(r[25]),"=r"(r[26]),"=r"(r[27]),"=r"(r[28]),"=r"(r[29]),"=r"(r[30]),"=r"(r[31])
        : "r"(a));
}
#endif

// ---------------- GEMM: C[m,n] = sum_k A[m,k]*B[n,k]; A fp16; B = NBL fp16 panels ----------------
// EPI: 0 fp32; 1 +bias relu -> fp16; 2 +bias fp32; 3 +addmat relu fp32; 4 Hebbian -> transposed hi/lo
template<int EPI, int NBL, int NST>
__global__ void __launch_bounds__(256, 1)
mma_gemm(const __half* __restrict__ A,
         const __half* __restrict__ Bh, const __half* __restrict__ Bl,
         int K, int ldC, float* __restrict__ C,
         const float* __restrict__ bias, const float* __restrict__ addmat,
         const float* __restrict__ Wold, const float* __restrict__ rmax,
         const float* __restrict__ rsum, const float* __restrict__ sdec,
         __half* __restrict__ Oh, __half* __restrict__ Ol) {
    extern __shared__ char dsm[];
    const int tid = threadIdx.x;
    const int m0 = blockIdx.x * 128, n0 = blockIdx.y * 128;
    constexpr int NP = 1 + NBL;
    constexpr int STAGE = NP * 16384;
    constexpr int L = NST - 1;

#if TC_OK
    __shared__ uint32_t s_tm;
    __shared__ __align__(8) uint64_t s_mb[NST];
    const int wid = tid >> 5, lid = tid & 31;
    uint32_t tile0 = (s2u(dsm) + 1023u) & ~1023u;
    uint32_t mbA[NST];
#pragma unroll
    for (int s = 0; s < NST; s++) mbA[s] = s2u(&s_mb[s]);

    if (wid == 0) {
        asm volatile("tcgen05.alloc.cta_group::1.sync.aligned.shared::cta.b32 [%0], %1;"
                     :: "r"(s2u(&s_tm)), "r"(128u) : "memory");
        asm volatile("tcgen05.relinquish_alloc_permit.cta_group::1.sync.aligned;");
    }
    if (tid == 0)
        for (int s = 0; s < NST; s++) mbar_init(mbA[s], 1);
    __syncthreads();
    const uint32_t tm = s_tm;

    const __half* srcs[3] = { A + (size_t)m0 * K, Bh + (size_t)n0 * K,
                              NBL == 2 ? Bl + (size_t)n0 * K : nullptr };

    const int NC = K >> 6;

#define DO_COPY(i)                                                              \
    do {                                                                        \
        uint32_t base_ = tile0 + ((i) % NST) * STAGE;                           \
        _Pragma("unroll")                                                       \
        for (int p = 0; p < NP; p++) {                                          \
            const __half* s_ = srcs[p] + (i) * 64;                              \
            uint32_t pb_ = base_ + p * 16384;                                   \
            _Pragma("unroll")                                                   \
            for (int t = 0; t < 4; t++) {                                       \
                int idx_ = tid + t * 256;                                       \
                int r_ = idx_ >> 3, c_ = idx_ & 7;                              \
                cp16(pb_ + sw128(r_ * 128 + c_ * 16), s_ + (size_t)r_ * K + c_ * 8); \
            }                                                                   \
        }                                                                       \
        asm volatile("cp.async.commit_group;" ::: "memory");                    \
    } while (0)

    for (int c = 0; c < L && c < NC; c++) DO_COPY(c);

    for (int i = 0; i < NC; i++) {
        if (i + L < NC) {
            if (i >= 1) mbar_wait(mbA[(i - 1) % NST], ((i - 1) / NST) & 1);
            DO_COPY(i + L);
        }
        int rem = NC - 1 - i; if (rem > L) rem = L;
        cp_wait_n(rem);
        __syncthreads();
        if (tid == 0) {
            asm volatile("fence.proxy.async.shared::cta;" ::: "memory");
            uint32_t base = tile0 + (i % NST) * STAGE;
            uint64_t ad = sdesc(base);
            uint64_t bh = sdesc(base + 16384);
            uint64_t bl = sdesc(base + 32768);
#pragma unroll
            for (int s4 = 0; s4 < 4; s4++) {
                mma_f16(tm, ad + 2*s4, bh + 2*s4, (i > 0) | (s4 > 0));
                if (NBL == 2) mma_f16(tm, ad + 2*s4, bl + 2*s4, 1);
            }
            mma_commit(mbA[i % NST]);
        }
    }
#undef DO_COPY

    for (int j = (NC >= NST ? NC - NST : 0); j < NC; j++)
        mbar_wait(mbA[j % NST], (j / NST) & 1);
    asm volatile("tcgen05.fence::after_thread_sync;" ::: "memory");

    if (wid < 4) {
        const int m = m0 + wid * 32 + lid;
        float sd = 0.f, rm = 0.f, irs = 1.f;
        if (EPI == 4) { sd = sdec[m]; rm = rmax[m]; irs = 1.f / rsum[m]; }
#pragma unroll
        for (int cb = 0; cb < 4; cb++) {
            uint32_t rr[32];
            ldtm32(rr, tm + cb * 32);
            asm volatile("tcgen05.wait::ld.sync.aligned;" ::: "memory");
            const int nb = n0 + cb * 32;
            if (EPI == 0) {
                float4* c4 = (float4*)(C + (size_t)m * ldC + nb);
#pragma unroll
                for (int q = 0; q < 8; q++)
                    c4[q] = make_float4(__uint_as_float(rr[4*q]), __uint_as_float(rr[4*q+1]),
                                        __uint_as_float(rr[4*q+2]), __uint_as_float(rr[4*q+3]));
            } else if (EPI == 1) {
#pragma unroll
                for (int j = 0; j < 32; j += 2) {
                    float v0 = fmaxf(__uint_as_float(rr[j])   + bias[nb+j],   0.f);
                    float v1 = fmaxf(__uint_as_float(rr[j+1]) + bias[nb+j+1], 0.f);
                    *(__half2*)(Oh + (size_t)m * ldC + nb + j) = __floats2half2_rn(v0, v1);
                }
            } else if (EPI == 2) {
                float4* c4 = (float4*)(C + (size_t)m * ldC + nb);
#pragma unroll
                for (int q = 0; q < 8; q++)
                    c4[q] = make_float4(__uint_as_float(rr[4*q])   + bias[nb+4*q],
                                        __uint_as_float(rr[4*q+1]) + bias[nb+4*q+1],
                                        __uint_as_float(rr[4*q+2]) + bias[nb+4*q+2],
                                        __uint_as_float(rr[4*q+3]) + bias[nb+4*q+3]);
            } else if (EPI == 3) {
                const float4* a4 = (const float4*)(addmat + (size_t)m * ldC + nb);
                float4* c4 = (float4*)(C + (size_t)m * ldC + nb);
#pragma unroll
                for (int q = 0; q < 8; q++) {
                    float4 a = a4[q];
                    c4[q] = make_float4(fmaxf(__uint_as_float(rr[4*q])   + a.x, 0.f),
                                        fmaxf(__uint_as_float(rr[4*q+1]) + a.y, 0.f),
                                        fmaxf(__uint_as_float(rr[4*q+2]) + a.z, 0.f),
                                        fmaxf(__uint_as_float(rr[4*q+3]) + a.w, 0.f));
                }
            } else {
                const float4* w4 = (const float4*)(Wold + (size_t)m * D + nb);
#pragma unroll
                for (int q = 0; q < 8; q++) {
                    float4 w = w4[q];
                    float wv[4] = { w.x, w.y, w.z, w.w };
#pragma unroll
                    for (int e = 0; e < 4; e++) {
                        int j = 4*q + e;
                        float p = expf(wv[e] - rm) * irs;
                        float o = wv[e] + p * (__uint_as_float(rr[j]) * (1.0f/BB)) - sd * wv[e];
                        __half hh, ll;
                        split2h(o, hh, ll);
                        Oh[(size_t)(nb + j) * D + m] = hh;
                        Ol[(size_t)(nb + j) * D + m] = ll;
                    }
                }
            }
        }
    }
    __syncthreads();
    if (wid == 0)
        asm volatile("tcgen05.dealloc.cta_group::1.sync.aligned.b32 %0, %1;" :: "r"(tm), "r"(128u));

#else  // ---------- generic-target fallback ----------
    float* As = (float*)dsm;
    float* Bs = As + 16 * 132;
    const int tx = tid & 15, ty = tid >> 4;
    float acc[8][8];
#pragma unroll
    for (int i = 0; i < 8; i++)
#pragma unroll
        for (int j = 0; j < 8; j++) acc[i][j] = 0.f;
    for (int k0 = 0; k0 < K; k0 += 16) {
#pragma unroll
        for (int e = 0; e < 8; e++) {
            int idx = tid + e * 256;
            int r = idx >> 4, k = idx & 15;
            size_t ai = (size_t)(m0 + r) * K + k0 + k;
            size_t bi = (size_t)(n0 + r) * K + k0 + k;
            As[k * 132 + r] = __half2float(A[ai]);
            float bv = __half2float(Bh[bi]);
            if (NBL == 2) bv += __half2float(Bl[bi]);
            Bs[k * 132 + r] = bv;
        }
        __syncthreads();
#pragma unroll
        for (int kk = 0; kk < 16; kk++) {
            float a[8], b[8];
#pragma unroll
            for (int i = 0; i < 8; i++) a[i] = As[kk * 132 + ty * 8 + i];
#pragma unroll
            for (int j = 0; j < 8; j++) b[j] = Bs[kk * 132 + tx * 8 + j];
#pragma unroll
            for (int i = 0; i < 8; i++)
#pragma unroll
                for (int j = 0; j < 8; j++) acc[i][j] = fmaf(a[i], b[j], acc[i][j]);
        }
        __syncthreads();
    }
#pragma unroll
    for (int i = 0; i < 8; i++) {
        int m = m0 + ty * 8 + i;
        float sd = 0.f, rm = 0.f, irs = 1.f;
        if (EPI == 4) { sd = sdec[m]; rm = rmax[m]; irs = 1.f / rsum[m]; }
#pragma unroll
        for (int j = 0; j < 8; j++) {
            int n = n0 + tx * 8 + j;
            float v = acc[i][j];
            if (EPI == 0) C[(size_t)m * ldC + n] = v;
            else if (EPI == 1) Oh[(size_t)m * ldC + n] = __float2half_rn(fmaxf(v + bias[n], 0.f));
            else if (EPI == 2) C[(size_t)m * ldC + n] = v + bias[n];
            else if (EPI == 3) C[(size_t)m * ldC + n] = fmaxf(v + addmat[(size_t)m * ldC + n], 0.f);
            else {
                float w = Wold[(size_t)m * D + n];
                float p = expf(w - rm) * irs;
                float o = w + p * (v * (1.0f/BB)) - sd * w;
                __half hh, ll; split2h(o, hh, ll);
                Oh[(size_t)n * D + m] = hh; Ol[(size_t)n * D + m] = ll;
            }
        }
    }
#endif
}

// ---------------- block reduce + elementwise ----------------
__device__ __forceinline__ float blk_reduce(float v, bool do_max) {
    __shared__ float sh[32];
    int lane = threadIdx.x & 31, w = threadIdx.x >> 5;
#pragma unroll
    for (int o = 16; o; o >>= 1) {
        float t = __shfl_xor_sync(0xffffffffu, v, o);
        v = do_max ? fmaxf(v, t) : v + t;
    }
    if (lane == 0) sh[w] = v;
    __syncthreads();
    if (w == 0) {
        v = (lane < (int)(blockDim.x >> 5)) ? sh[lane] : (do_max ? -INFINITY : 0.f);
#pragma unroll
        for (int o = 16; o; o >>= 1) {
            float t = __shfl_xor_sync(0xffffffffu, v, o);
            v = do_max ? fmaxf(v, t) : v + t;
        }
        if (lane == 0) sh[0] = v;
    }
    __syncthreads();
    float r = sh[0];
    __syncthreads();
    return r;
}

__global__ void row_stats_kernel(const float* __restrict__ src,
                                 float* __restrict__ rmax, float* __restrict__ rsum) {
    int row = blockIdx.x;
    const float* x = src + (size_t)row * D;
    float m = -INFINITY;
    for (int i = threadIdx.x; i < D; i += blockDim.x) m = fmaxf(m, x[i]);
    m = blk_reduce(m, true);
    float s = 0.f;
    for (int i = threadIdx.x; i < D; i += blockDim.x) s += expf(x[i] - m);
    s = blk_reduce(s, false);
    if (threadIdx.x == 0) { rmax[row] = m; rsum[row] = s; }
}

// softmax phase 2: transposed normalize, coalesced via smem tile. grid (D/32, BB/32)
__global__ void softmax_tn_kernel(const float* __restrict__ src,
                                  const float* __restrict__ rm, const float* __restrict__ rs,
                                  __half* __restrict__ dst) {
    __shared__ float tile[32][33];
    __shared__ float tm[32], ts[32];
    int i0 = blockIdx.x * 32, b0 = blockIdx.y * 32;
    int tx = threadIdx.x & 31, ty = threadIdx.x >> 5;
    if (threadIdx.x < 32) { tm[threadIdx.x] = rm[b0 + threadIdx.x]; ts[threadIdx.x] = 1.f / rs[b0 + threadIdx.x]; }
    __syncthreads();
#pragma unroll
    for (int r = ty; r < 32; r += 8)
        tile[r][tx] = src[(size_t)(b0 + r) * D + i0 + tx];
    __syncthreads();
#pragma unroll
    for (int r = ty; r < 32; r += 8)
        dst[(size_t)(i0 + r) * BB + b0 + tx] = __float2half_rn(expf(tile[tx][r] - tm[tx]) * ts[tx]);
}

__global__ void layernorm_kernel(const float* __restrict__ src,
                                 const float* __restrict__ g, const float* __restrict__ b,
                                 float* __restrict__ dst) {
    int row = blockIdx.x;
    const float* x = src + (size_t)row * D;
    float s = 0.f, s2 = 0.f;
    for (int i = threadIdx.x; i < D; i += blockDim.x) { float v = x[i]; s += v; s2 += v * v; }
    s = blk_reduce(s, false);
    s2 = blk_reduce(s2, false);
    float mean = s * (1.f / D);
    float rstd = rsqrtf(s2 * (1.f / D) - mean * mean + 1e-5f);
    for (int i = threadIdx.x; i < D; i += blockDim.x)
        dst[(size_t)row * D + i] = (x[i] - mean) * rstd * g[i] + b[i];
}

__global__ void zero_kernel(float* p, int n) {
    int i = blockIdx.x * blockDim.x + threadIdx.x;
    if (i < n) p[i] = 0.f;
}

// neuromod with smem-transposed coalesced maT store. grid (D/32, BB/64)
__global__ void neuromod_t(const float* __restrict__ nt,
                           const float* __restrict__ dopamine,
                           const float* __restrict__ serotonin,
                           const float* __restrict__ gaba,
                           const float* __restrict__ alpha,
                           __half* __restrict__ maT, float* __restrict__ gsum) {
    __shared__ float tile[64][33];
    int j0 = blockIdx.x * 32, b0 = blockIdx.y * 64;
    int tx = threadIdx.x & 31, ty = threadIdx.x >> 5;
    int j = j0 + tx;
    float a = alpha[j];
    float gs = 0.f;
    for (int bb = ty; bb < 64; bb += 8) {
        int b = b0 + bb;
        const float* p = nt + (size_t)b * N3;
        float pd = p[j], ps = p[D + j], pg = p[2*D + j];
        float inv = 1.f / fmaxf(ps, 1e-6f);
        size_t bi = (size_t)b * D + j;
        float dop = tanhf(dopamine[bi] + pd * inv);
        float ser = sigm(serotonin[bi] + ps);
        gs += sigm(gaba[bi] + pg * inv);
        tile[bb][tx] = a * dop * ser;
    }
    atomicAdd(&gsum[j], gs);
    __syncthreads();
    int c = threadIdx.x & 63, jy = threadIdx.x >> 6;
#pragma unroll
    for (int jj = jy; jj < 32; jj += 4)
        maT[(size_t)(j0 + jj) * BB + b0 + c] = __float2half_rn(tile[c][jj]);
}

__global__ void sdecay_kernel(const float* __restrict__ gsum,
                              const float* __restrict__ decay, float* __restrict__ sdec) {
    int j = blockIdx.x * blockDim.x + threadIdx.x;
    sdec[j] = decay[j] * sigm(gsum[j] * (1.f / BB));
}

__global__ void cvt_kernel(const float4* __restrict__ src, __half* __restrict__ dst, size_t n4) {
    size_t i = (size_t)blockIdx.x * blockDim.x + threadIdx.x;
    if (i >= n4) return;
    float4 v = src[i];
    ((__half2*)dst)[2*i]   = __floats2half2_rn(v.x, v.y);
    ((__half2*)dst)[2*i+1] = __floats2half2_rn(v.z, v.w);
}

__global__ void cvt_permute_kernel(const float* __restrict__ src, __half* __restrict__ dst) {
    int r = blockIdx.x;
    int c = r % 3, j = r / 3;
    const float4* s4 = (const float4*)(src + (size_t)r * D);
    __half2* d2 = (__half2*)(dst + (size_t)(c * D + j) * D);
    for (int i = threadIdx.x; i < D / 4; i += blockDim.x) {
        float4 v = s4[i];
        d2[2*i]   = __floats2half2_rn(v.x, v.y);
        d2[2*i+1] = __floats2half2_rn(v.z, v.w);
    }
}

__global__ void permute_bias_kernel(const float* __restrict__ src, float* __restrict__ dst) {
    int r = blockIdx.x * blockDim.x + threadIdx.x;
    if (r < N3) dst[(r % 3) * D + r / 3] = src[r];
}

// ---------------- host ----------------
template<typename T>
static void* sym_addr(T& sym) { void* p = nullptr; cudaGetSymbolAddress(&p, sym); return p; }
#define HF(sym) ((__half*)sym_addr(sym))
#define FP(sym) ((float*)sym_addr(sym))

extern "C" void kernel_launch(void* const* d_in, const int* in_sizes, int n_in,
                              void* d_out, int out_size) {
    const float* x        = (const float*)d_in[0];
    const float* prev_act = (const float*)d_in[1];
    const float* prev_rec = (const float*)d_in[2];
    const float* dopamine = (const float*)d_in[3];
    const float* serotonin= (const float*)d_in[4];
    const float* gaba     = (const float*)d_in[5];
    const float* W        = (const float*)d_in[6];
    const float* Wr       = (const float*)d_in[7];
    const float* alpha    = (const float*)d_in[8];
    const float* decay    = (const float*)d_in[9];
    const float* gact     = (const float*)d_in[10];
    const float* bact     = (const float*)d_in[11];
    const float* grec     = (const float*)d_in[12];
    const float* brec     = (const float*)d_in[13];
    const float* p1w      = (const float*)d_in[14];
    const float* p1b      = (const float*)d_in[15];
    const float* p2w      = (const float*)d_in[16];
    const float* p2b      = (const float*)d_in[17];
    float* out = (float*)d_out;

    const int SM1 = 2 * 16384 * 6 + 1024;   // NBL=1, NST=6
    const int SM2 = 3 * 16384 * 4 + 1024;   // NBL=2, NST=4

    static cudaStream_t s1, s2;
    static cudaEvent_t ev_root, ev_pa, ev_as, ev_p2, ev_sw, ev_ma, ev_wn, ev_ri;
    static bool init_done = false;
    if (!init_done) {
        cudaStreamCreateWithFlags(&s1, cudaStreamNonBlocking);
        cudaStreamCreateWithFlags(&s2, cudaStreamNonBlocking);
        cudaEventCreateWithFlags(&ev_root, cudaEventDisableTiming);
        cudaEventCreateWithFlags(&ev_pa, cudaEventDisableTiming);
        cudaEventCreateWithFlags(&ev_as, cudaEventDisableTiming);
        cudaEventCreateWithFlags(&ev_p2, cudaEventDisableTiming);
        cudaEventCreateWithFlags(&ev_sw, cudaEventDisableTiming);
        cudaEventCreateWithFlags(&ev_ma, cudaEventDisableTiming);
        cudaEventCreateWithFlags(&ev_wn, cudaEventDisableTiming);
        cudaEventCreateWithFlags(&ev_ri, cudaEventDisableTiming);
        cudaFuncSetAttribute((const void*)mma_gemm<1,1,6>, cudaFuncAttributeMaxDynamicSharedMemorySize, SM1);
        cudaFuncSetAttribute((const void*)mma_gemm<2,1,6>, cudaFuncAttributeMaxDynamicSharedMemorySize, SM1);
        cudaFuncSetAttribute((const void*)mma_gemm<4,1,6>, cudaFuncAttributeMaxDynamicSharedMemorySize, SM1);
        cudaFuncSetAttribute((const void*)mma_gemm<0,2,4>, cudaFuncAttributeMaxDynamicSharedMemorySize, SM2);
        cudaFuncSetAttribute((const void*)mma_gemm<3,2,4>, cudaFuncAttributeMaxDynamicSharedMemorySize, SM2);
        init_done = true;
    }

    // ---- FORK: side streams must join capture via an origin-stream event FIRST ----
    cudaEventRecord(ev_root, 0);
    cudaStreamWaitEvent(s1, ev_root, 0);
    cudaStreamWaitEvent(s2, ev_root, 0);

    // ---- s0: input converts ----
    cvt_kernel<<<(BB*D/4 + 255)/256, 256>>>((const float4*)prev_act, HF(g_pa), BB*D/4);
    cvt_kernel<<<(BB*D/4 + 255)/256, 256>>>((const float4*)x,        HF(g_x),  BB*D/4);
    cudaEventRecord(ev_pa, 0);

    // ---- s1: p1 convert -> GEMM1 ----
    cvt_kernel<<<((size_t)D*D/4 + 255)/256, 256, 0, s1>>>((const float4*)p1w, HF(g_p1), (size_t)D*D/4);
    cudaStreamWaitEvent(s1, ev_pa, 0);
    mma_gemm<1,1,6><<<dim3(BB/128, D/128), 256, SM1, s1>>>(
        HF(g_pa), HF(g_p1), nullptr, D, D,
        nullptr, p1b, nullptr, nullptr, nullptr, nullptr, nullptr, HF(g_h), nullptr);

    // ---- s2: p2 convert + W row stats ----
    cvt_permute_kernel<<<N3, 256, 0, s2>>>(p2w, HF(g_p2));
    permute_bias_kernel<<<(N3 + 255)/256, 256, 0, s2>>>(p2b, FP(g_p2b));
    cudaEventRecord(ev_p2, s2);
    row_stats_kernel<<<D, 256, 0, s2>>>(W,  FP(g_rmW), FP(g_rsW));
    cudaEventRecord(ev_sw, s2);
    row_stats_kernel<<<D, 256, 0, s2>>>(Wr, FP(g_rmR), FP(g_rsR));

    // ---- s0: transposed softmaxes ----
    row_stats_kernel<<<BB, 256>>>(prev_act, FP(g_mPA), FP(g_sPA));
    softmax_tn_kernel<<<dim3(D/32, BB/32), 256>>>(prev_act, FP(g_mPA), FP(g_sPA), HF(g_asT));
    row_stats_kernel<<<BB, 256>>>(prev_rec, FP(g_mPR), FP(g_sPR));
    softmax_tn_kernel<<<dim3(D/32, BB/32), 256>>>(prev_rec, FP(g_mPR), FP(g_sPR), HF(g_arsT));
    cudaEventRecord(ev_as, 0);

    // ---- s1: GEMM2 + neuromod + Hebbian-W ----
    cudaStreamWaitEvent(s1, ev_p2, 0);
    mma_gemm<2,1,6><<<dim3(BB/128, N3/128), 256, SM1, s1>>>(
        HF(g_h), HF(g_p2), nullptr, D, N3,
        FP(g_nt), FP(g_p2b), nullptr, nullptr, nullptr, nullptr, nullptr, nullptr, nullptr);
    zero_kernel<<<D/256, 256, 0, s1>>>(FP(g_gsum), D);
    neuromod_t<<<dim3(D/32, BB/64), 256, 0, s1>>>(FP(g_nt), dopamine, serotonin, gaba, alpha,
                                                  HF(g_maT), FP(g_gsum));
    sdecay_kernel<<<D/256, 256, 0, s1>>>(FP(g_gsum), decay, FP(g_sdec));
    cudaEventRecord(ev_ma, s1);
    cudaStreamWaitEvent(s1, ev_as, 0);
    cudaStreamWaitEvent(s1, ev_sw, 0);
    mma_gemm<4,1,6><<<dim3(D/128, D/128), 256, SM1, s1>>>(
        HF(g_asT), HF(g_maT), nullptr, BB, D,
        nullptr, nullptr, nullptr, W,  FP(g_rmW), FP(g_rsW), FP(g_sdec), HF(g_WnT_h), HF(g_WnT_l));
    cudaEventRecord(ev_wn, s1);

    // ---- s2: Hebbian-Wr + rec GEMM + LN ----
    cudaStreamWaitEvent(s2, ev_as, 0);
    cudaStreamWaitEvent(s2, ev_ma, 0);
    mma_gemm<4,1,6><<<dim3(D/128, D/128), 256, SM1, s2>>>(
        HF(g_arsT), HF(g_maT), nullptr, BB, D,
        nullptr, nullptr, nullptr, Wr, FP(g_rmR), FP(g_rsR), FP(g_sdec), HF(g_WrT_h), HF(g_WrT_l));
    cudaStreamWaitEvent(s2, ev_pa, 0);
    mma_gemm<0,2,4><<<dim3(BB/128, D/128), 256, SM2, s2>>>(
        HF(g_pa), HF(g_WrT_h), HF(g_WrT_l), D, D,
        FP(g_rec), nullptr, nullptr, nullptr, nullptr, nullptr, nullptr, nullptr, nullptr);
    layernorm_kernel<<<BB, 256, 0, s2>>>(FP(g_rec), grec, brec, FP(g_recin));
    cudaEventRecord(ev_ri, s2);

    // ---- s0: JOIN + final GEMM + LN ----
    cudaStreamWaitEvent(0, ev_wn, 0);
    cudaStreamWaitEvent(0, ev_ri, 0);
    mma_gemm<3,2,4><<<dim3(BB/128, D/128), 256, SM2>>>(
        HF(g_x), HF(g_WnT_h), HF(g_WnT_l), D, D,
        FP(g_act), nullptr, FP(g_recin), nullptr, nullptr, nullptr, nullptr, nullptr, nullptr);
    layernorm_kernel<<<BB, 256>>>(FP(g_act), gact, bact, out);
}